// round 1
// baseline (speedup 1.0000x reference)
#include <cuda_runtime.h>
#include <math.h>

#define B_      1024
#define P_      11
#define C_      8
#define H_      512
#define T_      200
#define L_      2000
#define STRIDE_ 180
#define M_      (B_*P_*C_)   // 90112 rows for the per-patch MLP

// ---------------- scratch (device globals; no allocation allowed) ----------------
__device__ float g_H[(size_t)M_ * H_];        // 184 MB  GELU(X@W1+b1)
__device__ float g_patches[(size_t)M_ * T_];  //  72 MB  H@W2+b2
__device__ float g_rec[(size_t)B_ * C_ * L_]; //  64 MB  overlap-add result
__device__ float g_r1[(size_t)B_ * 4*C_ * L_];// 256 MB  conv1 out
__device__ float g_r2[(size_t)B_ * 2*C_ * L_];// 128 MB  conv2 out

__device__ __forceinline__ float gelu_erf(float x) {
    return 0.5f * x * (1.0f + erff(x * 0.7071067811865476f));
}

// ---------------- fp32 tiled GEMM: C = act(A[MxK] @ B[KxN] + bias[N]) ----------------
// BM=BN=128, BK=8, 256 threads, 8x8 microtile per thread. M must be %128, K %8, N %4.
template<bool DOGELU>
__global__ void __launch_bounds__(256) gemm_bias_kernel(
    const float* __restrict__ A, const float* __restrict__ Bm,
    const float* __restrict__ bias, float* __restrict__ Cm,
    int M, int N, int K)
{
    __shared__ __align__(16) float As[8][128];
    __shared__ __align__(16) float Bs[8][128];

    const int bm = blockIdx.y * 128;
    const int bn = blockIdx.x * 128;
    const int tid = threadIdx.x;
    const int tx = tid & 15;
    const int ty = tid >> 4;

    const int arow = tid >> 1;         // 0..127
    const int acol = (tid & 1) * 4;    // 0 or 4
    const int brow = tid >> 5;         // 0..7
    const int bcol = (tid & 31) * 4;   // 0..124

    float acc[8][8];
#pragma unroll
    for (int i = 0; i < 8; i++)
#pragma unroll
        for (int j = 0; j < 8; j++) acc[i][j] = 0.0f;

    const float* Aptr = A + (size_t)(bm + arow) * K + acol;

    for (int k0 = 0; k0 < K; k0 += 8) {
        float4 av = *reinterpret_cast<const float4*>(Aptr + k0);
        As[acol + 0][arow] = av.x;
        As[acol + 1][arow] = av.y;
        As[acol + 2][arow] = av.z;
        As[acol + 3][arow] = av.w;

        float4 bv = make_float4(0.f, 0.f, 0.f, 0.f);
        if (bn + bcol < N)   // N%4==0 and bcol%4==0 => float4 fully in or out
            bv = *reinterpret_cast<const float4*>(&Bm[(size_t)(k0 + brow) * N + bn + bcol]);
        *reinterpret_cast<float4*>(&Bs[brow][bcol]) = bv;

        __syncthreads();
#pragma unroll
        for (int k = 0; k < 8; k++) {
            float a[8], b[8];
            *reinterpret_cast<float4*>(&a[0]) = *reinterpret_cast<const float4*>(&As[k][ty * 8]);
            *reinterpret_cast<float4*>(&a[4]) = *reinterpret_cast<const float4*>(&As[k][ty * 8 + 4]);
            *reinterpret_cast<float4*>(&b[0]) = *reinterpret_cast<const float4*>(&Bs[k][tx * 8]);
            *reinterpret_cast<float4*>(&b[4]) = *reinterpret_cast<const float4*>(&Bs[k][tx * 8 + 4]);
#pragma unroll
            for (int i = 0; i < 8; i++)
#pragma unroll
                for (int j = 0; j < 8; j++)
                    acc[i][j] += a[i] * b[j];
        }
        __syncthreads();
    }

#pragma unroll
    for (int i = 0; i < 8; i++) {
        size_t row = (size_t)bm + ty * 8 + i;   // M%128==0 -> always in range
#pragma unroll
        for (int j = 0; j < 8; j++) {
            int col = bn + tx * 8 + j;
            if (col < N) {
                float v = acc[i][j] + bias[col];
                if (DOGELU) v = gelu_erf(v);
                Cm[row * N + col] = v;
            }
        }
    }
}

// ---------------- overlap-add with triangular-fade window ----------------
__global__ void overlap_add_kernel(const float* __restrict__ patches,
                                   float* __restrict__ rec)
{
    int idx = blockIdx.x * 256 + threadIdx.x;       // over B*C*L
    if (idx >= B_ * C_ * L_) return;
    int l  = idx % L_;
    int bc = idx / L_;
    int c  = bc & (C_ - 1);
    int b  = bc >> 3;

    int i_lo = l - (T_ - 1);
    i_lo = (i_lo > 0) ? (i_lo + STRIDE_ - 1) / STRIDE_ : 0;
    int i_hi = l / STRIDE_;
    if (i_hi > P_ - 1) i_hi = P_ - 1;

    float acc = 0.0f, ws = 0.0f;
    for (int i = i_lo; i <= i_hi; i++) {
        int t = l - i * STRIDE_;
        float w;
        if (t < 50)        w = (float)t * (1.0f / 49.0f);
        else if (t >= 150) w = (float)(199 - t) * (1.0f / 49.0f);
        else               w = 1.0f;
        acc += patches[(((size_t)b * P_ + i) * C_ + c) * T_ + t] * w;
        ws  += w;
    }
    rec[idx] = acc / fmaxf(ws, 1e-8f);
}

// ---------------- direct conv1d k=15 pad=7, register-blocked ----------------
// 64 threads/block, each thread owns 4 consecutive positions; OCG out-channels
// per accumulation pass. Input tile staged in smem with halo.
template<int CIN, int COUT, int OCG, bool DOGELU>
__global__ void __launch_bounds__(64) conv15_kernel(
    const float* __restrict__ in, const float* __restrict__ wt,
    const float* __restrict__ bias, float* __restrict__ out)
{
    constexpr int TILE = 256;
    constexpr int SROW = TILE + 16;
    __shared__ __align__(16) float sbuf[CIN][SROW];

    const int b     = blockIdx.y;
    const int tile0 = blockIdx.x * TILE;
    const int tid   = threadIdx.x;

    const float* inb = in + (size_t)b * CIN * L_;
    for (int idx = tid; idx < CIN * SROW; idx += 64) {
        int ic = idx / SROW, j = idx % SROW;
        int l = tile0 - 7 + j;
        sbuf[ic][j] = (l >= 0 && l < L_) ? inb[(size_t)ic * L_ + l] : 0.0f;
    }
    __syncthreads();

    const int lp = tid * 4;
    const int l0 = tile0 + lp;

#pragma unroll
    for (int ocg = 0; ocg < COUT / OCG; ocg++) {
        float acc[OCG][4];
#pragma unroll
        for (int o = 0; o < OCG; o++) {
            float bv = bias[ocg * OCG + o];
            acc[o][0] = bv; acc[o][1] = bv; acc[o][2] = bv; acc[o][3] = bv;
        }
        for (int ic = 0; ic < CIN; ic++) {
            float x[20];
            const float4* xp = reinterpret_cast<const float4*>(&sbuf[ic][lp]);
#pragma unroll
            for (int q = 0; q < 5; q++) {
                float4 v = xp[q];
                x[q*4+0] = v.x; x[q*4+1] = v.y; x[q*4+2] = v.z; x[q*4+3] = v.w;
            }
#pragma unroll
            for (int o = 0; o < OCG; o++) {
                const float* wp = wt + ((size_t)(ocg * OCG + o) * CIN + ic) * 15;
#pragma unroll
                for (int k = 0; k < 15; k++) {
                    float wv = __ldg(wp + k);
                    acc[o][0] += wv * x[k + 0];
                    acc[o][1] += wv * x[k + 1];
                    acc[o][2] += wv * x[k + 2];
                    acc[o][3] += wv * x[k + 3];
                }
            }
        }
#pragma unroll
        for (int o = 0; o < OCG; o++)
#pragma unroll
            for (int p = 0; p < 4; p++) {
                int l = l0 + p;
                if (l < L_) {
                    float v = acc[o][p];
                    if (DOGELU) v = gelu_erf(v);
                    out[((size_t)b * COUT + ocg * OCG + o) * L_ + l] = v;
                }
            }
    }
}

// ---------------- conv3 (16->8,k15) + residual + pointwise 8->8, fused ----------------
__global__ void __launch_bounds__(64) conv3_res_pw_kernel(
    const float* __restrict__ in, const float* __restrict__ wt,
    const float* __restrict__ bias, const float* __restrict__ rec,
    const float* __restrict__ pw, const float* __restrict__ pb,
    float* __restrict__ out)
{
    constexpr int CIN = 16, TILE = 256, SROW = TILE + 16;
    __shared__ __align__(16) float sbuf[CIN][SROW];

    const int b     = blockIdx.y;
    const int tile0 = blockIdx.x * TILE;
    const int tid   = threadIdx.x;

    const float* inb = in + (size_t)b * CIN * L_;
    for (int idx = tid; idx < CIN * SROW; idx += 64) {
        int ic = idx / SROW, j = idx % SROW;
        int l = tile0 - 7 + j;
        sbuf[ic][j] = (l >= 0 && l < L_) ? inb[(size_t)ic * L_ + l] : 0.0f;
    }
    __syncthreads();

    const int lp = tid * 4;
    const int l0 = tile0 + lp;

    float acc[8][4];
#pragma unroll
    for (int o = 0; o < 8; o++) {
        float bv = bias[o];
        acc[o][0] = bv; acc[o][1] = bv; acc[o][2] = bv; acc[o][3] = bv;
    }
    for (int ic = 0; ic < CIN; ic++) {
        float x[20];
        const float4* xp = reinterpret_cast<const float4*>(&sbuf[ic][lp]);
#pragma unroll
        for (int q = 0; q < 5; q++) {
            float4 v = xp[q];
            x[q*4+0] = v.x; x[q*4+1] = v.y; x[q*4+2] = v.z; x[q*4+3] = v.w;
        }
#pragma unroll
        for (int o = 0; o < 8; o++) {
            const float* wp = wt + ((size_t)o * CIN + ic) * 15;
#pragma unroll
            for (int k = 0; k < 15; k++) {
                float wv = __ldg(wp + k);
                acc[o][0] += wv * x[k + 0];
                acc[o][1] += wv * x[k + 1];
                acc[o][2] += wv * x[k + 2];
                acc[o][3] += wv * x[k + 3];
            }
        }
    }

    // residual add
    float recf[8][4];
#pragma unroll
    for (int o = 0; o < 8; o++)
#pragma unroll
        for (int p = 0; p < 4; p++) {
            int l = l0 + p;
            recf[o][p] = (l < L_) ? rec[((size_t)b * C_ + o) * L_ + l] + acc[o][p] : 0.0f;
        }

    // pointwise Conv1d(C,C,1)
#pragma unroll
    for (int o = 0; o < 8; o++) {
        float r0 = pb[o], r1 = r0, r2 = r0, r3 = r0;
#pragma unroll
        for (int c = 0; c < 8; c++) {
            float wv = __ldg(&pw[o * C_ + c]);
            r0 += wv * recf[c][0];
            r1 += wv * recf[c][1];
            r2 += wv * recf[c][2];
            r3 += wv * recf[c][3];
        }
        size_t base = ((size_t)b * C_ + o) * L_;
        if (l0 + 0 < L_) out[base + l0 + 0] = r0;
        if (l0 + 1 < L_) out[base + l0 + 1] = r1;
        if (l0 + 2 < L_) out[base + l0 + 2] = r2;
        if (l0 + 3 < L_) out[base + l0 + 3] = r3;
    }
}

// ---------------- launcher ----------------
extern "C" void kernel_launch(void* const* d_in, const int* in_sizes, int n_in,
                              void* d_out, int out_size)
{
    const float* X   = (const float*)d_in[0];   // (B,P,C,H) = (90112,512)
    const float* W1  = (const float*)d_in[1];   // (512,512)
    const float* b1  = (const float*)d_in[2];   // (512,)
    const float* W2  = (const float*)d_in[3];   // (512,200)
    const float* b2  = (const float*)d_in[4];   // (200,)
    const float* rw1 = (const float*)d_in[5];   // (32,8,15)
    const float* rb1 = (const float*)d_in[6];
    const float* rw2 = (const float*)d_in[7];   // (16,32,15)
    const float* rb2 = (const float*)d_in[8];
    const float* rw3 = (const float*)d_in[9];   // (8,16,15)
    const float* rb3 = (const float*)d_in[10];
    const float* pw  = (const float*)d_in[11];  // (8,8,1)
    const float* pb  = (const float*)d_in[12];
    float* out = (float*)d_out;

    float *pH, *pPatches, *pRec, *pR1, *pR2;
    cudaGetSymbolAddress((void**)&pH,       g_H);
    cudaGetSymbolAddress((void**)&pPatches, g_patches);
    cudaGetSymbolAddress((void**)&pRec,     g_rec);
    cudaGetSymbolAddress((void**)&pR1,      g_r1);
    cudaGetSymbolAddress((void**)&pR2,      g_r2);

    // 1) H = GELU(X @ W1 + b1)
    {
        dim3 grid((H_ + 127) / 128, M_ / 128);
        gemm_bias_kernel<true><<<grid, 256>>>(X, W1, b1, pH, M_, H_, H_);
    }
    // 2) patches = H @ W2 + b2
    {
        dim3 grid((T_ + 127) / 128, M_ / 128);
        gemm_bias_kernel<false><<<grid, 256>>>(pH, W2, b2, pPatches, M_, T_, H_);
    }
    // 3) overlap-add -> rec
    {
        int total = B_ * C_ * L_;
        overlap_add_kernel<<<(total + 255) / 256, 256>>>(pPatches, pRec);
    }
    // 4) r1 = GELU(conv1(rec))   8 -> 32
    {
        dim3 grid((L_ + 255) / 256, B_);
        conv15_kernel<8, 32, 16, true><<<grid, 64>>>(pRec, rw1, rb1, pR1);
    }
    // 5) r2 = GELU(conv2(r1))    32 -> 16
    {
        dim3 grid((L_ + 255) / 256, B_);
        conv15_kernel<32, 16, 16, true><<<grid, 64>>>(pR1, rw2, rb2, pR2);
    }
    // 6) out = pw @ (rec + conv3(r2)) + pb
    {
        dim3 grid((L_ + 255) / 256, B_);
        conv3_res_pw_kernel<<<grid, 64>>>(pR2, rw3, rb3, pRec, pw, pb, out);
    }
}

// round 2
// speedup vs baseline: 1.7100x; 1.7100x over previous
#include <cuda_runtime.h>
#include <math.h>

#define B_      1024
#define P_      11
#define C_      8
#define H_      512
#define T_      200
#define L_      2000
#define STRIDE_ 180
#define M_      (B_*P_*C_)   // 90112 rows for the per-patch MLP

typedef unsigned long long u64;

// ---------------- scratch (device globals; no allocation allowed) ----------------
__device__ float g_H[(size_t)M_ * H_];        // 184 MB  GELU(X@W1+b1)
__device__ float g_patches[(size_t)M_ * T_];  //  72 MB  H@W2+b2
__device__ float g_rec[(size_t)B_ * C_ * L_]; //  64 MB  overlap-add result
__device__ float g_r1[(size_t)B_ * 4*C_ * L_];// 256 MB  conv1 out
__device__ float g_r2[(size_t)B_ * 2*C_ * L_];// 128 MB  conv2 out
// packed conv weights: [COUT/2][CIN][16] f32x2 pairs (k padded 15->16)
__device__ u64 g_wp1[16 * 8  * 16];
__device__ u64 g_wp2[8  * 32 * 16];
__device__ u64 g_wp3[4  * 16 * 16];

__device__ __forceinline__ float gelu_erf(float x) {
    return 0.5f * x * (1.0f + erff(x * 0.7071067811865476f));
}

// ---------------- f32x2 packed-pair helpers ----------------
__device__ __forceinline__ u64 pack2(float lo, float hi) {
    u64 r; asm("mov.b64 %0, {%1, %2};" : "=l"(r) : "f"(lo), "f"(hi)); return r;
}
__device__ __forceinline__ u64 bcast2(float v) { return pack2(v, v); }
__device__ __forceinline__ void fma2(u64& d, u64 a, u64 b) {
    asm("fma.rn.f32x2 %0, %1, %2, %0;" : "+l"(d) : "l"(a), "l"(b));
}
__device__ __forceinline__ float2 unpack2(u64 d) {
    float2 r; asm("mov.b64 {%0, %1}, %2;" : "=f"(r.x), "=f"(r.y) : "l"(d)); return r;
}

// ---------------- weight pair packing (tiny prep kernel) ----------------
// w: (COUT, CIN, 15) -> wp: (COUT/2, CIN, 16) of (w[2o],w[2o+1]) pairs
__global__ void pack_w_kernel(const float* __restrict__ w, float2* __restrict__ wp,
                              int COUT, int CIN)
{
    int idx = blockIdx.x * 128 + threadIdx.x;
    int total = (COUT / 2) * CIN * 16;
    if (idx >= total) return;
    int k  = idx & 15;
    int t  = idx >> 4;
    int ic = t % CIN;
    int op = t / CIN;
    float lo = 0.0f, hi = 0.0f;
    if (k < 15) {
        lo = w[((size_t)(2 * op)     * CIN + ic) * 15 + k];
        hi = w[((size_t)(2 * op + 1) * CIN + ic) * 15 + k];
    }
    wp[idx] = make_float2(lo, hi);
}

// ---------------- fp32 GEMM with packed f32x2 FMA ----------------
// C = act(A[MxK] @ B[KxN] + bias). BM=BN=128, BK=8, 256 thr, 8x8 microtile.
// A staged duplicated in smem so broadcast pairs load as 64-bit LDS.
template<bool DOGELU>
__global__ void __launch_bounds__(256) gemm_bias_f32x2(
    const float* __restrict__ A, const float* __restrict__ Bm,
    const float* __restrict__ bias, float* __restrict__ Cm,
    int M, int N, int K)
{
    __shared__ __align__(16) float As[8][256];   // duplicated pairs (a,a)
    __shared__ __align__(16) float Bs[8][128];

    const int bm = blockIdx.y * 128;
    const int bn = blockIdx.x * 128;
    const int tid = threadIdx.x;
    const int tx = tid & 15;
    const int ty = tid >> 4;

    const int arow = tid >> 1;
    const int acol = (tid & 1) * 4;
    const int brow = tid >> 5;
    const int bcol = (tid & 31) * 4;

    u64 acc[8][4];
#pragma unroll
    for (int i = 0; i < 8; i++)
#pragma unroll
        for (int j = 0; j < 4; j++) {
            int col = bn + tx * 8 + 2 * j;
            acc[i][j] = (col < N) ? pack2(bias[col], bias[col + 1]) : 0ULL;
        }

    const float* Aptr = A + (size_t)(bm + arow) * K + acol;

    for (int k0 = 0; k0 < K; k0 += 8) {
        float4 av = *reinterpret_cast<const float4*>(Aptr + k0);
        *reinterpret_cast<float2*>(&As[acol + 0][2 * arow]) = make_float2(av.x, av.x);
        *reinterpret_cast<float2*>(&As[acol + 1][2 * arow]) = make_float2(av.y, av.y);
        *reinterpret_cast<float2*>(&As[acol + 2][2 * arow]) = make_float2(av.z, av.z);
        *reinterpret_cast<float2*>(&As[acol + 3][2 * arow]) = make_float2(av.w, av.w);

        float4 bv = make_float4(0.f, 0.f, 0.f, 0.f);
        if (bn + bcol < N)
            bv = *reinterpret_cast<const float4*>(&Bm[(size_t)(k0 + brow) * N + bn + bcol]);
        *reinterpret_cast<float4*>(&Bs[brow][bcol]) = bv;

        __syncthreads();
#pragma unroll
        for (int k = 0; k < 8; k++) {
            u64 a[8], b[4];
            const ulonglong2* ad = reinterpret_cast<const ulonglong2*>(&As[k][ty * 16]);
            const ulonglong2* bd = reinterpret_cast<const ulonglong2*>(&Bs[k][tx * 8]);
#pragma unroll
            for (int q = 0; q < 4; q++) { ulonglong2 t = ad[q]; a[2*q] = t.x; a[2*q+1] = t.y; }
#pragma unroll
            for (int q = 0; q < 2; q++) { ulonglong2 t = bd[q]; b[2*q] = t.x; b[2*q+1] = t.y; }
#pragma unroll
            for (int i = 0; i < 8; i++)
#pragma unroll
                for (int j = 0; j < 4; j++)
                    fma2(acc[i][j], a[i], b[j]);
        }
        __syncthreads();
    }

#pragma unroll
    for (int i = 0; i < 8; i++) {
        size_t row = (size_t)bm + ty * 8 + i;   // M%128==0
#pragma unroll
        for (int j = 0; j < 4; j++) {
            int col = bn + tx * 8 + 2 * j;
            if (col < N) {                       // N even -> pair fully in/out
                float2 v = unpack2(acc[i][j]);
                if (DOGELU) { v.x = gelu_erf(v.x); v.y = gelu_erf(v.y); }
                *reinterpret_cast<float2*>(&Cm[row * N + col]) = v;
            }
        }
    }
}

// ---------------- overlap-add with triangular-fade window ----------------
__global__ void overlap_add_kernel(const float* __restrict__ patches,
                                   float* __restrict__ rec)
{
    int idx = blockIdx.x * 256 + threadIdx.x;       // over B*C*L
    if (idx >= B_ * C_ * L_) return;
    int l  = idx % L_;
    int bc = idx / L_;
    int c  = bc & (C_ - 1);
    int b  = bc >> 3;

    int i_lo = l - (T_ - 1);
    i_lo = (i_lo > 0) ? (i_lo + STRIDE_ - 1) / STRIDE_ : 0;
    int i_hi = l / STRIDE_;
    if (i_hi > P_ - 1) i_hi = P_ - 1;

    float acc = 0.0f, ws = 0.0f;
    for (int i = i_lo; i <= i_hi; i++) {
        int t = l - i * STRIDE_;
        float w;
        if (t < 50)        w = (float)t * (1.0f / 49.0f);
        else if (t >= 150) w = (float)(199 - t) * (1.0f / 49.0f);
        else               w = 1.0f;
        acc += patches[(((size_t)b * P_ + i) * C_ + c) * T_ + t] * w;
        ws  += w;
    }
    rec[idx] = acc / fmaxf(ws, 1e-8f);
}

// ---------------- conv1d k=15 pad=7, f32x2 with o-channel pairing ----------------
// 128 threads, 4 positions each (TILE=512). OPG pairs of out-channels per pass.
template<int CIN, int COUT, int OPG, bool DOGELU>
__global__ void __launch_bounds__(128) conv15_f32x2(
    const float* __restrict__ in, const u64* __restrict__ wp,
    const float* __restrict__ bias, float* __restrict__ out)
{
    constexpr int THREADS = 128;
    constexpr int TILE = THREADS * 4;   // 512
    constexpr int SROW = TILE + 16;     // 528
    __shared__ __align__(16) float sbuf[CIN][SROW];

    const int b     = blockIdx.y;
    const int tile0 = blockIdx.x * TILE;
    const int tid   = threadIdx.x;

    const float* inb = in + (size_t)b * CIN * L_;
    for (int idx = tid; idx < CIN * SROW; idx += THREADS) {
        int ic = idx / SROW, j = idx - ic * SROW;
        int l = tile0 - 7 + j;
        sbuf[ic][j] = (l >= 0 && l < L_) ? inb[(size_t)ic * L_ + l] : 0.0f;
    }
    __syncthreads();

    const int lp = tid * 4;
    const int l0 = tile0 + lp;
    constexpr int NPASS = (COUT / 2) / OPG;

#pragma unroll
    for (int pass = 0; pass < NPASS; pass++) {
        u64 acc[OPG][4];
#pragma unroll
        for (int o = 0; o < OPG; o++) {
            int ch = 2 * (pass * OPG + o);
            u64 bv = pack2(bias[ch], bias[ch + 1]);
            acc[o][0] = bv; acc[o][1] = bv; acc[o][2] = bv; acc[o][3] = bv;
        }
        for (int ic = 0; ic < CIN; ic++) {
            float x[20];
            const float4* xp = reinterpret_cast<const float4*>(&sbuf[ic][lp]);
#pragma unroll
            for (int q = 0; q < 5; q++) {
                float4 v = xp[q];
                x[4*q+0] = v.x; x[4*q+1] = v.y; x[4*q+2] = v.z; x[4*q+3] = v.w;
            }
            u64 xb[18];
#pragma unroll
            for (int j = 0; j < 18; j++) xb[j] = bcast2(x[j]);
#pragma unroll
            for (int o = 0; o < OPG; o++) {
                const ulonglong2* w2 = reinterpret_cast<const ulonglong2*>(
                    wp + ((size_t)(pass * OPG + o) * CIN + ic) * 16);
                u64 wr[16];
#pragma unroll
                for (int q = 0; q < 8; q++) { ulonglong2 t = w2[q]; wr[2*q] = t.x; wr[2*q+1] = t.y; }
#pragma unroll
                for (int k = 0; k < 15; k++) {
                    fma2(acc[o][0], wr[k], xb[k + 0]);
                    fma2(acc[o][1], wr[k], xb[k + 1]);
                    fma2(acc[o][2], wr[k], xb[k + 2]);
                    fma2(acc[o][3], wr[k], xb[k + 3]);
                }
            }
        }
#pragma unroll
        for (int o = 0; o < OPG; o++) {
            int ch = 2 * (pass * OPG + o);
#pragma unroll
            for (int p = 0; p < 4; p++) {
                int l = l0 + p;
                if (l < L_) {
                    float2 v = unpack2(acc[o][p]);
                    if (DOGELU) { v.x = gelu_erf(v.x); v.y = gelu_erf(v.y); }
                    out[((size_t)b * COUT + ch    ) * L_ + l] = v.x;
                    out[((size_t)b * COUT + ch + 1) * L_ + l] = v.y;
                }
            }
        }
    }
}

// ---------------- conv3 (16->8,k15) + residual + pointwise 8->8, fused, f32x2 ----------------
__global__ void __launch_bounds__(128) conv3_res_pw_f32x2(
    const float* __restrict__ in, const u64* __restrict__ wp,
    const float* __restrict__ bias, const float* __restrict__ rec,
    const float* __restrict__ pw, const float* __restrict__ pb,
    float* __restrict__ out)
{
    constexpr int CIN = 16, THREADS = 128, TILE = THREADS * 4, SROW = TILE + 16;
    __shared__ __align__(16) float sbuf[CIN][SROW];

    const int b     = blockIdx.y;
    const int tile0 = blockIdx.x * TILE;
    const int tid   = threadIdx.x;

    const float* inb = in + (size_t)b * CIN * L_;
    for (int idx = tid; idx < CIN * SROW; idx += THREADS) {
        int ic = idx / SROW, j = idx - ic * SROW;
        int l = tile0 - 7 + j;
        sbuf[ic][j] = (l >= 0 && l < L_) ? inb[(size_t)ic * L_ + l] : 0.0f;
    }
    __syncthreads();

    const int lp = tid * 4;
    const int l0 = tile0 + lp;

    u64 acc[4][4];   // 4 channel-pairs x 4 positions
#pragma unroll
    for (int o = 0; o < 4; o++) {
        u64 bv = pack2(bias[2*o], bias[2*o + 1]);
        acc[o][0] = bv; acc[o][1] = bv; acc[o][2] = bv; acc[o][3] = bv;
    }
    for (int ic = 0; ic < CIN; ic++) {
        float x[20];
        const float4* xp = reinterpret_cast<const float4*>(&sbuf[ic][lp]);
#pragma unroll
        for (int q = 0; q < 5; q++) {
            float4 v = xp[q];
            x[4*q+0] = v.x; x[4*q+1] = v.y; x[4*q+2] = v.z; x[4*q+3] = v.w;
        }
        u64 xb[18];
#pragma unroll
        for (int j = 0; j < 18; j++) xb[j] = bcast2(x[j]);
#pragma unroll
        for (int o = 0; o < 4; o++) {
            const ulonglong2* w2 = reinterpret_cast<const ulonglong2*>(
                wp + ((size_t)o * CIN + ic) * 16);
            u64 wr[16];
#pragma unroll
            for (int q = 0; q < 8; q++) { ulonglong2 t = w2[q]; wr[2*q] = t.x; wr[2*q+1] = t.y; }
#pragma unroll
            for (int k = 0; k < 15; k++) {
                fma2(acc[o][0], wr[k], xb[k + 0]);
                fma2(acc[o][1], wr[k], xb[k + 1]);
                fma2(acc[o][2], wr[k], xb[k + 2]);
                fma2(acc[o][3], wr[k], xb[k + 3]);
            }
        }
    }

    // residual add: recf[channel][position]
    float recf[8][4];
#pragma unroll
    for (int o = 0; o < 4; o++)
#pragma unroll
        for (int p = 0; p < 4; p++) {
            int l = l0 + p;
            float2 v = unpack2(acc[o][p]);
            if (l < L_) {
                recf[2*o    ][p] = rec[((size_t)b * C_ + 2*o    ) * L_ + l] + v.x;
                recf[2*o + 1][p] = rec[((size_t)b * C_ + 2*o + 1) * L_ + l] + v.y;
            } else {
                recf[2*o][p] = 0.0f; recf[2*o + 1][p] = 0.0f;
            }
        }

    // pointwise Conv1d(C,C,1)
#pragma unroll
    for (int o = 0; o < 8; o++) {
        float r0 = pb[o], r1 = r0, r2 = r0, r3 = r0;
#pragma unroll
        for (int c = 0; c < 8; c++) {
            float wv = __ldg(&pw[o * C_ + c]);
            r0 += wv * recf[c][0];
            r1 += wv * recf[c][1];
            r2 += wv * recf[c][2];
            r3 += wv * recf[c][3];
        }
        size_t base = ((size_t)b * C_ + o) * L_;
        if (l0 + 0 < L_) out[base + l0 + 0] = r0;
        if (l0 + 1 < L_) out[base + l0 + 1] = r1;
        if (l0 + 2 < L_) out[base + l0 + 2] = r2;
        if (l0 + 3 < L_) out[base + l0 + 3] = r3;
    }
}

// ---------------- launcher ----------------
extern "C" void kernel_launch(void* const* d_in, const int* in_sizes, int n_in,
                              void* d_out, int out_size)
{
    const float* X   = (const float*)d_in[0];   // (B,P,C,H) = (90112,512)
    const float* W1  = (const float*)d_in[1];   // (512,512)
    const float* b1  = (const float*)d_in[2];
    const float* W2  = (const float*)d_in[3];   // (512,200)
    const float* b2  = (const float*)d_in[4];
    const float* rw1 = (const float*)d_in[5];   // (32,8,15)
    const float* rb1 = (const float*)d_in[6];
    const float* rw2 = (const float*)d_in[7];   // (16,32,15)
    const float* rb2 = (const float*)d_in[8];
    const float* rw3 = (const float*)d_in[9];   // (8,16,15)
    const float* rb3 = (const float*)d_in[10];
    const float* pw  = (const float*)d_in[11];  // (8,8,1)
    const float* pb  = (const float*)d_in[12];
    float* out = (float*)d_out;

    float *pH, *pPatches, *pRec, *pR1, *pR2;
    u64 *pWp1, *pWp2, *pWp3;
    cudaGetSymbolAddress((void**)&pH,       g_H);
    cudaGetSymbolAddress((void**)&pPatches, g_patches);
    cudaGetSymbolAddress((void**)&pRec,     g_rec);
    cudaGetSymbolAddress((void**)&pR1,      g_r1);
    cudaGetSymbolAddress((void**)&pR2,      g_r2);
    cudaGetSymbolAddress((void**)&pWp1,     g_wp1);
    cudaGetSymbolAddress((void**)&pWp2,     g_wp2);
    cudaGetSymbolAddress((void**)&pWp3,     g_wp3);

    // 0) pack conv weights into f32x2 pairs
    pack_w_kernel<<<(16*8*16  + 127) / 128, 128>>>(rw1, (float2*)pWp1, 32, 8);
    pack_w_kernel<<<(8*32*16  + 127) / 128, 128>>>(rw2, (float2*)pWp2, 16, 32);
    pack_w_kernel<<<(4*16*16  + 127) / 128, 128>>>(rw3, (float2*)pWp3, 8, 16);

    // 1) H = GELU(X @ W1 + b1)
    {
        dim3 grid((H_ + 127) / 128, M_ / 128);
        gemm_bias_f32x2<true><<<grid, 256>>>(X, W1, b1, pH, M_, H_, H_);
    }
    // 2) patches = H @ W2 + b2
    {
        dim3 grid((T_ + 127) / 128, M_ / 128);
        gemm_bias_f32x2<false><<<grid, 256>>>(pH, W2, b2, pPatches, M_, T_, H_);
    }
    // 3) overlap-add -> rec
    {
        int total = B_ * C_ * L_;
        overlap_add_kernel<<<(total + 255) / 256, 256>>>(pPatches, pRec);
    }
    // 4) r1 = GELU(conv1(rec))   8 -> 32
    {
        dim3 grid((L_ + 511) / 512, B_);
        conv15_f32x2<8, 32, 4, true><<<grid, 128>>>(pRec, pWp1, rb1, pR1);
    }
    // 5) r2 = GELU(conv2(r1))    32 -> 16
    {
        dim3 grid((L_ + 511) / 512, B_);
        conv15_f32x2<32, 16, 4, true><<<grid, 128>>>(pR1, pWp2, rb2, pR2);
    }
    // 6) out = pw @ (rec + conv3(r2)) + pb
    {
        dim3 grid((L_ + 511) / 512, B_);
        conv3_res_pw_f32x2<<<grid, 128>>>(pR2, pWp3, rb3, pRec, pw, pb, out);
    }
}

// round 3
// speedup vs baseline: 1.9222x; 1.1241x over previous
#include <cuda_runtime.h>
#include <math.h>

#define B_      1024
#define P_      11
#define C_      8
#define H_      512
#define T_      200
#define L_      2000
#define STRIDE_ 180
#define M_      (B_*P_*C_)   // 90112 rows for the per-patch MLP

typedef unsigned long long u64;

// ---------------- scratch (device globals; no allocation allowed) ----------------
__device__ float g_H[(size_t)M_ * H_];        // 184 MB  GELU(X@W1+b1)
__device__ float g_patches[(size_t)M_ * T_];  //  72 MB  H@W2+b2
__device__ float g_rec[(size_t)B_ * C_ * L_]; //  64 MB  overlap-add result
__device__ float g_r1[(size_t)B_ * 4*C_ * L_];// 256 MB  conv1 out
__device__ float g_r2[(size_t)B_ * 2*C_ * L_];// 128 MB  conv2 out
// packed conv weights: [COUT/2][CIN][16] f32x2 pairs (k padded 15->16)
__device__ u64 g_wp1[16 * 8  * 16];
__device__ u64 g_wp2[8  * 32 * 16];
__device__ u64 g_wp3[4  * 16 * 16];

__device__ __forceinline__ float gelu_erf(float x) {
    return 0.5f * x * (1.0f + erff(x * 0.7071067811865476f));
}

// ---------------- f32x2 packed-pair helpers ----------------
__device__ __forceinline__ u64 pack2(float lo, float hi) {
    u64 r; asm("mov.b64 %0, {%1, %2};" : "=l"(r) : "f"(lo), "f"(hi)); return r;
}
__device__ __forceinline__ u64 bcast2(float v) { return pack2(v, v); }
__device__ __forceinline__ void fma2(u64& d, u64 a, u64 b) {
    asm("fma.rn.f32x2 %0, %1, %2, %0;" : "+l"(d) : "l"(a), "l"(b));
}
__device__ __forceinline__ float2 unpack2(u64 d) {
    float2 r; asm("mov.b64 {%0, %1}, %2;" : "=f"(r.x), "=f"(r.y) : "l"(d)); return r;
}

// ---------------- weight pair packing (tiny prep kernel) ----------------
__global__ void pack_w_kernel(const float* __restrict__ w, float2* __restrict__ wp,
                              int COUT, int CIN)
{
    int idx = blockIdx.x * 128 + threadIdx.x;
    int total = (COUT / 2) * CIN * 16;
    if (idx >= total) return;
    int k  = idx & 15;
    int t  = idx >> 4;
    int ic = t % CIN;
    int op = t / CIN;
    float lo = 0.0f, hi = 0.0f;
    if (k < 15) {
        lo = w[((size_t)(2 * op)     * CIN + ic) * 15 + k];
        hi = w[((size_t)(2 * op + 1) * CIN + ic) * 15 + k];
    }
    wp[idx] = make_float2(lo, hi);
}

// ---------------- fp32 GEMM v3: f32x2 FMA, BK=16, double-buffered smem ----------------
// C = act(A[MxK] @ B[KxN] + bias). BM=BN=128, 256 thr, 8x8 microtile.
// A stored plain in smem; (a,a) pairs built with register MOVs (alu pipe has slack).
template<bool DOGELU>
__global__ void __launch_bounds__(256, 2) gemm_bias_f32x2(
    const float* __restrict__ A, const float* __restrict__ Bm,
    const float* __restrict__ bias, float* __restrict__ Cm,
    int M, int N, int K)
{
    __shared__ __align__(16) float As[2][16][128];
    __shared__ __align__(16) float Bs[2][16][128];

    const int bm = blockIdx.y * 128;
    const int bn = blockIdx.x * 128;
    const int tid = threadIdx.x;
    const int tx = tid & 15;
    const int ty = tid >> 4;

    // A-load mapping: each thread loads 8 floats of one row
    const int arow = tid >> 1;            // 0..127
    const int acol = (tid & 1) * 8;       // 0 or 8
    // B-load mapping: each thread loads 8 floats of one k-row
    const int brow = tid >> 4;            // 0..15
    const int bcol = (tid & 15) * 8;      // 0..120

    u64 acc[8][4];
#pragma unroll
    for (int i = 0; i < 8; i++)
#pragma unroll
        for (int j = 0; j < 4; j++) {
            int col = bn + tx * 8 + 2 * j;
            acc[i][j] = (col < N) ? pack2(bias[col], bias[col + 1]) : 0ULL;
        }

    const float* Aptr = A + (size_t)(bm + arow) * K + acol;
    const int nkb = K >> 4;

    float4 pa0, pa1, pb0, pb1;
    // prefetch block 0
    pa0 = *reinterpret_cast<const float4*>(Aptr + 0);
    pa1 = *reinterpret_cast<const float4*>(Aptr + 4);
    {
        int c0 = bn + bcol, c1 = bn + bcol + 4;
        pb0 = (c0 < N) ? *reinterpret_cast<const float4*>(&Bm[(size_t)brow * N + c0])
                       : make_float4(0.f,0.f,0.f,0.f);
        pb1 = (c1 < N) ? *reinterpret_cast<const float4*>(&Bm[(size_t)brow * N + c1])
                       : make_float4(0.f,0.f,0.f,0.f);
    }
    // store block 0
    {
        As[0][acol+0][arow]=pa0.x; As[0][acol+1][arow]=pa0.y;
        As[0][acol+2][arow]=pa0.z; As[0][acol+3][arow]=pa0.w;
        As[0][acol+4][arow]=pa1.x; As[0][acol+5][arow]=pa1.y;
        As[0][acol+6][arow]=pa1.z; As[0][acol+7][arow]=pa1.w;
        *reinterpret_cast<float4*>(&Bs[0][brow][bcol])     = pb0;
        *reinterpret_cast<float4*>(&Bs[0][brow][bcol + 4]) = pb1;
    }
    __syncthreads();

    for (int kb = 0; kb < nkb; kb++) {
        const int cur = kb & 1, nxt = cur ^ 1;
        const bool more = (kb + 1 < nkb);
        if (more) {
            int koff = (kb + 1) << 4;
            pa0 = *reinterpret_cast<const float4*>(Aptr + koff);
            pa1 = *reinterpret_cast<const float4*>(Aptr + koff + 4);
            int c0 = bn + bcol, c1 = bn + bcol + 4;
            pb0 = (c0 < N) ? *reinterpret_cast<const float4*>(&Bm[(size_t)(koff + brow) * N + c0])
                           : make_float4(0.f,0.f,0.f,0.f);
            pb1 = (c1 < N) ? *reinterpret_cast<const float4*>(&Bm[(size_t)(koff + brow) * N + c1])
                           : make_float4(0.f,0.f,0.f,0.f);
        }

#pragma unroll
        for (int k = 0; k < 16; k++) {
            float ar[8];
            u64 b[4];
            *reinterpret_cast<float4*>(&ar[0]) = *reinterpret_cast<const float4*>(&As[cur][k][ty * 8]);
            *reinterpret_cast<float4*>(&ar[4]) = *reinterpret_cast<const float4*>(&As[cur][k][ty * 8 + 4]);
            const ulonglong2* bd = reinterpret_cast<const ulonglong2*>(&Bs[cur][k][tx * 8]);
            { ulonglong2 t = bd[0]; b[0] = t.x; b[1] = t.y; }
            { ulonglong2 t = bd[1]; b[2] = t.x; b[3] = t.y; }
            u64 a[8];
#pragma unroll
            for (int i = 0; i < 8; i++) a[i] = bcast2(ar[i]);
#pragma unroll
            for (int i = 0; i < 8; i++)
#pragma unroll
                for (int j = 0; j < 4; j++)
                    fma2(acc[i][j], a[i], b[j]);
        }

        if (more) {
            As[nxt][acol+0][arow]=pa0.x; As[nxt][acol+1][arow]=pa0.y;
            As[nxt][acol+2][arow]=pa0.z; As[nxt][acol+3][arow]=pa0.w;
            As[nxt][acol+4][arow]=pa1.x; As[nxt][acol+5][arow]=pa1.y;
            As[nxt][acol+6][arow]=pa1.z; As[nxt][acol+7][arow]=pa1.w;
            *reinterpret_cast<float4*>(&Bs[nxt][brow][bcol])     = pb0;
            *reinterpret_cast<float4*>(&Bs[nxt][brow][bcol + 4]) = pb1;
        }
        __syncthreads();
    }

#pragma unroll
    for (int i = 0; i < 8; i++) {
        size_t row = (size_t)bm + ty * 8 + i;   // M%128==0
#pragma unroll
        for (int j = 0; j < 4; j++) {
            int col = bn + tx * 8 + 2 * j;
            if (col < N) {                       // N even -> pair fully in/out
                float2 v = unpack2(acc[i][j]);
                if (DOGELU) { v.x = gelu_erf(v.x); v.y = gelu_erf(v.y); }
                *reinterpret_cast<float2*>(&Cm[row * N + col]) = v;
            }
        }
    }
}

// ---------------- overlap-add with triangular-fade window ----------------
__global__ void overlap_add_kernel(const float* __restrict__ patches,
                                   float* __restrict__ rec)
{
    int idx = blockIdx.x * 256 + threadIdx.x;       // over B*C*L
    if (idx >= B_ * C_ * L_) return;
    int l  = idx % L_;
    int bc = idx / L_;
    int c  = bc & (C_ - 1);
    int b  = bc >> 3;

    int i_lo = l - (T_ - 1);
    i_lo = (i_lo > 0) ? (i_lo + STRIDE_ - 1) / STRIDE_ : 0;
    int i_hi = l / STRIDE_;
    if (i_hi > P_ - 1) i_hi = P_ - 1;

    float acc = 0.0f, ws = 0.0f;
    for (int i = i_lo; i <= i_hi; i++) {
        int t = l - i * STRIDE_;
        float w;
        if (t < 50)        w = (float)t * (1.0f / 49.0f);
        else if (t >= 150) w = (float)(199 - t) * (1.0f / 49.0f);
        else               w = 1.0f;
        acc += patches[(((size_t)b * P_ + i) * C_ + c) * T_ + t] * w;
        ws  += w;
    }
    rec[idx] = acc / fmaxf(ws, 1e-8f);
}

// ---------------- conv1d k=15 pad=7, f32x2 with o-channel pairing ----------------
template<int CIN, int COUT, int OPG, bool DOGELU>
__global__ void __launch_bounds__(128) conv15_f32x2(
    const float* __restrict__ in, const u64* __restrict__ wp,
    const float* __restrict__ bias, float* __restrict__ out)
{
    constexpr int THREADS = 128;
    constexpr int TILE = THREADS * 4;   // 512
    constexpr int SROW = TILE + 16;     // 528
    __shared__ __align__(16) float sbuf[CIN][SROW];

    const int b     = blockIdx.y;
    const int tile0 = blockIdx.x * TILE;
    const int tid   = threadIdx.x;

    const float* inb = in + (size_t)b * CIN * L_;
    for (int idx = tid; idx < CIN * SROW; idx += THREADS) {
        int ic = idx / SROW, j = idx - ic * SROW;
        int l = tile0 - 7 + j;
        sbuf[ic][j] = (l >= 0 && l < L_) ? inb[(size_t)ic * L_ + l] : 0.0f;
    }
    __syncthreads();

    const int lp = tid * 4;
    const int l0 = tile0 + lp;
    constexpr int NPASS = (COUT / 2) / OPG;

#pragma unroll
    for (int pass = 0; pass < NPASS; pass++) {
        u64 acc[OPG][4];
#pragma unroll
        for (int o = 0; o < OPG; o++) {
            int ch = 2 * (pass * OPG + o);
            u64 bv = pack2(bias[ch], bias[ch + 1]);
            acc[o][0] = bv; acc[o][1] = bv; acc[o][2] = bv; acc[o][3] = bv;
        }
        for (int ic = 0; ic < CIN; ic++) {
            float x[20];
            const float4* xp = reinterpret_cast<const float4*>(&sbuf[ic][lp]);
#pragma unroll
            for (int q = 0; q < 5; q++) {
                float4 v = xp[q];
                x[4*q+0] = v.x; x[4*q+1] = v.y; x[4*q+2] = v.z; x[4*q+3] = v.w;
            }
            u64 xb[18];
#pragma unroll
            for (int j = 0; j < 18; j++) xb[j] = bcast2(x[j]);
#pragma unroll
            for (int o = 0; o < OPG; o++) {
                const ulonglong2* w2 = reinterpret_cast<const ulonglong2*>(
                    wp + ((size_t)(pass * OPG + o) * CIN + ic) * 16);
                u64 wr[16];
#pragma unroll
                for (int q = 0; q < 8; q++) { ulonglong2 t = w2[q]; wr[2*q] = t.x; wr[2*q+1] = t.y; }
#pragma unroll
                for (int k = 0; k < 15; k++) {
                    fma2(acc[o][0], wr[k], xb[k + 0]);
                    fma2(acc[o][1], wr[k], xb[k + 1]);
                    fma2(acc[o][2], wr[k], xb[k + 2]);
                    fma2(acc[o][3], wr[k], xb[k + 3]);
                }
            }
        }
#pragma unroll
        for (int o = 0; o < OPG; o++) {
            int ch = 2 * (pass * OPG + o);
#pragma unroll
            for (int p = 0; p < 4; p++) {
                int l = l0 + p;
                if (l < L_) {
                    float2 v = unpack2(acc[o][p]);
                    if (DOGELU) { v.x = gelu_erf(v.x); v.y = gelu_erf(v.y); }
                    out[((size_t)b * COUT + ch    ) * L_ + l] = v.x;
                    out[((size_t)b * COUT + ch + 1) * L_ + l] = v.y;
                }
            }
        }
    }
}

// ---------------- conv3 (16->8,k15) + residual + pointwise 8->8, fused, f32x2 ----------------
__global__ void __launch_bounds__(128) conv3_res_pw_f32x2(
    const float* __restrict__ in, const u64* __restrict__ wp,
    const float* __restrict__ bias, const float* __restrict__ rec,
    const float* __restrict__ pw, const float* __restrict__ pb,
    float* __restrict__ out)
{
    constexpr int CIN = 16, THREADS = 128, TILE = THREADS * 4, SROW = TILE + 16;
    __shared__ __align__(16) float sbuf[CIN][SROW];

    const int b     = blockIdx.y;
    const int tile0 = blockIdx.x * TILE;
    const int tid   = threadIdx.x;

    const float* inb = in + (size_t)b * CIN * L_;
    for (int idx = tid; idx < CIN * SROW; idx += THREADS) {
        int ic = idx / SROW, j = idx - ic * SROW;
        int l = tile0 - 7 + j;
        sbuf[ic][j] = (l >= 0 && l < L_) ? inb[(size_t)ic * L_ + l] : 0.0f;
    }
    __syncthreads();

    const int lp = tid * 4;
    const int l0 = tile0 + lp;

    u64 acc[4][4];
#pragma unroll
    for (int o = 0; o < 4; o++) {
        u64 bv = pack2(bias[2*o], bias[2*o + 1]);
        acc[o][0] = bv; acc[o][1] = bv; acc[o][2] = bv; acc[o][3] = bv;
    }
    for (int ic = 0; ic < CIN; ic++) {
        float x[20];
        const float4* xp = reinterpret_cast<const float4*>(&sbuf[ic][lp]);
#pragma unroll
        for (int q = 0; q < 5; q++) {
            float4 v = xp[q];
            x[4*q+0] = v.x; x[4*q+1] = v.y; x[4*q+2] = v.z; x[4*q+3] = v.w;
        }
        u64 xb[18];
#pragma unroll
        for (int j = 0; j < 18; j++) xb[j] = bcast2(x[j]);
#pragma unroll
        for (int o = 0; o < 4; o++) {
            const ulonglong2* w2 = reinterpret_cast<const ulonglong2*>(
                wp + ((size_t)o * CIN + ic) * 16);
            u64 wr[16];
#pragma unroll
            for (int q = 0; q < 8; q++) { ulonglong2 t = w2[q]; wr[2*q] = t.x; wr[2*q+1] = t.y; }
#pragma unroll
            for (int k = 0; k < 15; k++) {
                fma2(acc[o][0], wr[k], xb[k + 0]);
                fma2(acc[o][1], wr[k], xb[k + 1]);
                fma2(acc[o][2], wr[k], xb[k + 2]);
                fma2(acc[o][3], wr[k], xb[k + 3]);
            }
        }
    }

    float recf[8][4];
#pragma unroll
    for (int o = 0; o < 4; o++)
#pragma unroll
        for (int p = 0; p < 4; p++) {
            int l = l0 + p;
            float2 v = unpack2(acc[o][p]);
            if (l < L_) {
                recf[2*o    ][p] = rec[((size_t)b * C_ + 2*o    ) * L_ + l] + v.x;
                recf[2*o + 1][p] = rec[((size_t)b * C_ + 2*o + 1) * L_ + l] + v.y;
            } else {
                recf[2*o][p] = 0.0f; recf[2*o + 1][p] = 0.0f;
            }
        }

#pragma unroll
    for (int o = 0; o < 8; o++) {
        float r0 = pb[o], r1 = r0, r2 = r0, r3 = r0;
#pragma unroll
        for (int c = 0; c < 8; c++) {
            float wv = __ldg(&pw[o * C_ + c]);
            r0 += wv * recf[c][0];
            r1 += wv * recf[c][1];
            r2 += wv * recf[c][2];
            r3 += wv * recf[c][3];
        }
        size_t base = ((size_t)b * C_ + o) * L_;
        if (l0 + 0 < L_) out[base + l0 + 0] = r0;
        if (l0 + 1 < L_) out[base + l0 + 1] = r1;
        if (l0 + 2 < L_) out[base + l0 + 2] = r2;
        if (l0 + 3 < L_) out[base + l0 + 3] = r3;
    }
}

// ---------------- launcher ----------------
extern "C" void kernel_launch(void* const* d_in, const int* in_sizes, int n_in,
                              void* d_out, int out_size)
{
    const float* X   = (const float*)d_in[0];
    const float* W1  = (const float*)d_in[1];
    const float* b1  = (const float*)d_in[2];
    const float* W2  = (const float*)d_in[3];
    const float* b2  = (const float*)d_in[4];
    const float* rw1 = (const float*)d_in[5];
    const float* rb1 = (const float*)d_in[6];
    const float* rw2 = (const float*)d_in[7];
    const float* rb2 = (const float*)d_in[8];
    const float* rw3 = (const float*)d_in[9];
    const float* rb3 = (const float*)d_in[10];
    const float* pw  = (const float*)d_in[11];
    const float* pb  = (const float*)d_in[12];
    float* out = (float*)d_out;

    float *pH, *pPatches, *pRec, *pR1, *pR2;
    u64 *pWp1, *pWp2, *pWp3;
    cudaGetSymbolAddress((void**)&pH,       g_H);
    cudaGetSymbolAddress((void**)&pPatches, g_patches);
    cudaGetSymbolAddress((void**)&pRec,     g_rec);
    cudaGetSymbolAddress((void**)&pR1,      g_r1);
    cudaGetSymbolAddress((void**)&pR2,      g_r2);
    cudaGetSymbolAddress((void**)&pWp1,     g_wp1);
    cudaGetSymbolAddress((void**)&pWp2,     g_wp2);
    cudaGetSymbolAddress((void**)&pWp3,     g_wp3);

    // 0) pack conv weights into f32x2 pairs
    pack_w_kernel<<<(16*8*16  + 127) / 128, 128>>>(rw1, (float2*)pWp1, 32, 8);
    pack_w_kernel<<<(8*32*16  + 127) / 128, 128>>>(rw2, (float2*)pWp2, 16, 32);
    pack_w_kernel<<<(4*16*16  + 127) / 128, 128>>>(rw3, (float2*)pWp3, 8, 16);

    // 1) H = GELU(X @ W1 + b1)
    {
        dim3 grid((H_ + 127) / 128, M_ / 128);
        gemm_bias_f32x2<true><<<grid, 256>>>(X, W1, b1, pH, M_, H_, H_);
    }
    // 2) patches = H @ W2 + b2
    {
        dim3 grid((T_ + 127) / 128, M_ / 128);
        gemm_bias_f32x2<false><<<grid, 256>>>(pH, W2, b2, pPatches, M_, T_, H_);
    }
    // 3) overlap-add -> rec
    {
        int total = B_ * C_ * L_;
        overlap_add_kernel<<<(total + 255) / 256, 256>>>(pPatches, pRec);
    }
    // 4) r1 = GELU(conv1(rec))   8 -> 32
    {
        dim3 grid((L_ + 511) / 512, B_);
        conv15_f32x2<8, 32, 4, true><<<grid, 128>>>(pRec, pWp1, rb1, pR1);
    }
    // 5) r2 = GELU(conv2(r1))    32 -> 16
    {
        dim3 grid((L_ + 511) / 512, B_);
        conv15_f32x2<32, 16, 4, true><<<grid, 128>>>(pR1, pWp2, rb2, pR2);
    }
    // 6) out = pw @ (rec + conv3(r2)) + pb
    {
        dim3 grid((L_ + 511) / 512, B_);
        conv3_res_pw_f32x2<<<grid, 128>>>(pR2, pWp3, rb3, pRec, pw, pb, out);
    }
}

// round 5
// speedup vs baseline: 2.5312x; 1.3168x over previous
#include <cuda_runtime.h>
#include <cuda_bf16.h>
#include <math.h>
#include <stdint.h>

#define B_      1024
#define P_      11
#define C_      8
#define H_      512
#define T_      200
#define L_      2000
#define STRIDE_ 180
#define M_      (B_*P_*C_)   // 90112 rows for the per-patch MLP

typedef unsigned long long u64;
typedef unsigned int u32;

// ---------------- scratch (device globals; no allocation allowed) ----------------
__device__ __nv_bfloat16 g_Xh[(size_t)M_ * 512];   // 92 MB
__device__ __nv_bfloat16 g_Xl[(size_t)M_ * 512];
__device__ __nv_bfloat16 g_Hh[(size_t)M_ * 512];
__device__ __nv_bfloat16 g_Hl[(size_t)M_ * 512];
__device__ __nv_bfloat16 g_W1th[512 * 512];
__device__ __nv_bfloat16 g_W1tl[512 * 512];
__device__ __nv_bfloat16 g_W2th[256 * 512];
__device__ __nv_bfloat16 g_W2tl[256 * 512];
__device__ float g_patches[(size_t)M_ * T_];       //  72 MB
__device__ float g_rec[(size_t)B_ * C_ * L_];      //  64 MB
__device__ float g_r1[(size_t)B_ * 4*C_ * L_];     // 256 MB
__device__ float g_r2[(size_t)B_ * 2*C_ * L_];     // 128 MB
// packed conv weights: [COUT/2][CIN][16] f32x2 pairs
__device__ u64 g_wp1[16 * 8  * 16];
__device__ u64 g_wp2[8  * 32 * 16];
__device__ u64 g_wp3[4  * 16 * 16];

__device__ __forceinline__ float gelu_erf(float x) {
    return 0.5f * x * (1.0f + erff(x * 0.7071067811865476f));
}

// ---------------- warp MMA primitives (target-portable PTX) ----------------
__device__ __forceinline__ uint32_t smem_u32(const void* p) {
    uint32_t a;
    asm("{ .reg .u64 t; cvta.to.shared.u64 t, %1; cvt.u32.u64 %0, t; }" : "=r"(a) : "l"(p));
    return a;
}
__device__ __forceinline__ void ldsm_x4(u32& r0, u32& r1, u32& r2, u32& r3, u32 addr) {
    asm volatile("ldmatrix.sync.aligned.m8n8.x4.shared.b16 {%0,%1,%2,%3}, [%4];"
        : "=r"(r0), "=r"(r1), "=r"(r2), "=r"(r3) : "r"(addr));
}
__device__ __forceinline__ void mma_bf16(float* d, const u32* a, const u32* b) {
    asm volatile("mma.sync.aligned.m16n8k16.row.col.f32.bf16.bf16.f32 "
        "{%0,%1,%2,%3}, {%4,%5,%6,%7}, {%8,%9}, {%0,%1,%2,%3};"
        : "+f"(d[0]), "+f"(d[1]), "+f"(d[2]), "+f"(d[3])
        : "r"(a[0]), "r"(a[1]), "r"(a[2]), "r"(a[3]), "r"(b[0]), "r"(b[1]));
}

// ================= prep kernels =================
__global__ void split_f32_kernel(const float* __restrict__ x,
                                 __nv_bfloat16* __restrict__ hh,
                                 __nv_bfloat16* __restrict__ hl, int n4)
{
    int i = blockIdx.x * 256 + threadIdx.x;
    if (i >= n4) return;
    float4 v = reinterpret_cast<const float4*>(x)[i];
    float f[4] = {v.x, v.y, v.z, v.w};
    __nv_bfloat16 h[4], l[4];
#pragma unroll
    for (int j = 0; j < 4; j++) {
        h[j] = __float2bfloat16(f[j]);
        l[j] = __float2bfloat16(f[j] - __bfloat162float(h[j]));
    }
    __nv_bfloat162* ph = reinterpret_cast<__nv_bfloat162*>(hh) + 2 * (size_t)i;
    __nv_bfloat162* pl = reinterpret_cast<__nv_bfloat162*>(hl) + 2 * (size_t)i;
    ph[0] = __halves2bfloat162(h[0], h[1]); ph[1] = __halves2bfloat162(h[2], h[3]);
    pl[0] = __halves2bfloat162(l[0], l[1]); pl[1] = __halves2bfloat162(l[2], l[3]);
}

// W [K][Nsrc] fp32 -> Wt [Npad][K] bf16 hi/lo (transpose + split, zero-pad rows)
__global__ void transp_split_kernel(const float* __restrict__ W,
                                    __nv_bfloat16* __restrict__ th,
                                    __nv_bfloat16* __restrict__ tl,
                                    int Kdim, int Nsrc, int Npad)
{
    int idx = blockIdx.x * 256 + threadIdx.x;
    if (idx >= Npad * Kdim) return;
    int n = idx / Kdim, k = idx - n * Kdim;
    float f = (n < Nsrc) ? W[(size_t)k * Nsrc + n] : 0.0f;
    __nv_bfloat16 h = __float2bfloat16(f);
    th[idx] = h;
    tl[idx] = __float2bfloat16(f - __bfloat162float(h));
}

// ================= HMMA GEMM (mma.sync bf16, 3-way split) =================
// D[M,N] = act(A @ B^T + bias).  A = Ah+Al bf16 [M][512]; B^T = Bh/Bl [Npad][512].
// Block 128x64, 8 warps (4m x 2n), warp tile 32x32, BK=32, K=512.
// GELU_SPLIT: out = bf16-split(gelu(D)) into outHh/outHl (row stride 512);
// else: out = fp32 D into outF [M][Nvalid], cols >= Nvalid dropped.
#define ASTR 40   // smem row stride in bf16 (32 + 8 pad)

template<bool GELU_SPLIT>
__global__ void __launch_bounds__(256, 2) gemm_hmma(
    const __nv_bfloat16* __restrict__ Ah, const __nv_bfloat16* __restrict__ Al,
    const __nv_bfloat16* __restrict__ Bh, const __nv_bfloat16* __restrict__ Bl,
    const float* __restrict__ bias, int Nvalid,
    __nv_bfloat16* __restrict__ outHh, __nv_bfloat16* __restrict__ outHl,
    float* __restrict__ outF)
{
    __shared__ __align__(16) __nv_bfloat16 sAh[128 * ASTR];
    __shared__ __align__(16) __nv_bfloat16 sAl[128 * ASTR];
    __shared__ __align__(16) __nv_bfloat16 sBh[64 * ASTR];
    __shared__ __align__(16) __nv_bfloat16 sBl[64 * ASTR];

    const int tid  = threadIdx.x;
    const int lane = tid & 31;
    const int wid  = tid >> 5;
    const int wm   = wid & 3;            // 0..3  (m-warp)
    const int wn   = wid >> 2;           // 0..1  (n-warp)
    const int bm   = blockIdx.y * 128;
    const int bn   = blockIdx.x * 64;

    float acc[2][4][4];
#pragma unroll
    for (int i = 0; i < 2; i++)
#pragma unroll
        for (int j = 0; j < 4; j++)
#pragma unroll
            for (int q = 0; q < 4; q++) acc[i][j][q] = 0.0f;

    // gmem tile-load mapping
    const int ar = tid >> 2;             // 0..63 (A rows ar, ar+64)
    const int aq = (tid & 3) * 8;        // k-offset in bf16
    const size_t gA0 = (size_t)(bm + ar) * 512 + aq;
    const size_t gA1 = (size_t)(bm + ar + 64) * 512 + aq;
    const size_t gB0 = (size_t)(bn + ar) * 512 + aq;

    const u32 sbAh = smem_u32(sAh), sbAl = smem_u32(sAl);
    const u32 sbBh = smem_u32(sBh), sbBl = smem_u32(sBl);

    // ldmatrix addresses (byte offsets within smem arrays)
    const int lrow = lane & 15;
    const int lhalf = (lane >> 4) * 8;
    const u32 aoffA0 = ((wm * 32 +      lrow) * ASTR + lhalf) * 2;
    const u32 aoffA1 = ((wm * 32 + 16 + lrow) * ASTR + lhalf) * 2;
    const u32 aoffB0 = ((wn * 32 +      lrow) * ASTR + lhalf) * 2;
    const u32 aoffB1 = ((wn * 32 + 16 + lrow) * ASTR + lhalf) * 2;

    uint4 pah0, pah1, pal0, pal1, pbh, pbl;
    // prefetch tile 0
    pah0 = *(const uint4*)(Ah + gA0); pah1 = *(const uint4*)(Ah + gA1);
    pal0 = *(const uint4*)(Al + gA0); pal1 = *(const uint4*)(Al + gA1);
    pbh  = *(const uint4*)(Bh + gB0); pbl  = *(const uint4*)(Bl + gB0);

    const int sA0 = ar * ASTR + aq, sA1 = (ar + 64) * ASTR + aq, sB0 = ar * ASTR + aq;

    for (int kt = 0; kt < 16; kt++) {
        *(uint4*)(sAh + sA0) = pah0; *(uint4*)(sAh + sA1) = pah1;
        *(uint4*)(sAl + sA0) = pal0; *(uint4*)(sAl + sA1) = pal1;
        *(uint4*)(sBh + sB0) = pbh;  *(uint4*)(sBl + sB0) = pbl;
        __syncthreads();

        if (kt < 15) {
            int k0 = (kt + 1) * 32;
            pah0 = *(const uint4*)(Ah + gA0 + k0); pah1 = *(const uint4*)(Ah + gA1 + k0);
            pal0 = *(const uint4*)(Al + gA0 + k0); pal1 = *(const uint4*)(Al + gA1 + k0);
            pbh  = *(const uint4*)(Bh + gB0 + k0); pbl  = *(const uint4*)(Bl + gB0 + k0);
        }

#pragma unroll
        for (int kk = 0; kk < 2; kk++) {
            const u32 kadd = kk * 32;   // 16 bf16 = 32 bytes
            u32 a_h[2][4], a_l[2][4];
            ldsm_x4(a_h[0][0], a_h[0][1], a_h[0][2], a_h[0][3], sbAh + aoffA0 + kadd);
            ldsm_x4(a_h[1][0], a_h[1][1], a_h[1][2], a_h[1][3], sbAh + aoffA1 + kadd);
            ldsm_x4(a_l[0][0], a_l[0][1], a_l[0][2], a_l[0][3], sbAl + aoffA0 + kadd);
            ldsm_x4(a_l[1][0], a_l[1][1], a_l[1][2], a_l[1][3], sbAl + aoffA1 + kadd);

            u32 t0, t1, t2, t3;
            u32 b_h[4][2], b_l[4][2];
            ldsm_x4(t0, t1, t2, t3, sbBh + aoffB0 + kadd);
            b_h[0][0] = t0; b_h[0][1] = t2; b_h[1][0] = t1; b_h[1][1] = t3;
            ldsm_x4(t0, t1, t2, t3, sbBh + aoffB1 + kadd);
            b_h[2][0] = t0; b_h[2][1] = t2; b_h[3][0] = t1; b_h[3][1] = t3;
            ldsm_x4(t0, t1, t2, t3, sbBl + aoffB0 + kadd);
            b_l[0][0] = t0; b_l[0][1] = t2; b_l[1][0] = t1; b_l[1][1] = t3;
            ldsm_x4(t0, t1, t2, t3, sbBl + aoffB1 + kadd);
            b_l[2][0] = t0; b_l[2][1] = t2; b_l[3][0] = t1; b_l[3][1] = t3;

#pragma unroll
            for (int mi = 0; mi < 2; mi++)
#pragma unroll
                for (int ni = 0; ni < 4; ni++) {
                    mma_bf16(acc[mi][ni], a_h[mi], b_h[ni]);  // hh
                    mma_bf16(acc[mi][ni], a_h[mi], b_l[ni]);  // hl
                    mma_bf16(acc[mi][ni], a_l[mi], b_h[ni]);  // lh
                }
        }
        __syncthreads();
    }

    // ---- epilogue ----
    const int grp = lane >> 2;           // 0..7
    const int qc  = (lane & 3) * 2;
#pragma unroll
    for (int mi = 0; mi < 2; mi++) {
        const int r0 = bm + wm * 32 + mi * 16 + grp;
        const int r1 = r0 + 8;
#pragma unroll
        for (int ni = 0; ni < 4; ni++) {
            const int col = bn + wn * 32 + ni * 8 + qc;
            float bv0 = __ldg(&bias[col]), bv1 = __ldg(&bias[col + 1]);
            float v00 = acc[mi][ni][0] + bv0, v01 = acc[mi][ni][1] + bv1;
            float v10 = acc[mi][ni][2] + bv0, v11 = acc[mi][ni][3] + bv1;
            if (GELU_SPLIT) {
                v00 = gelu_erf(v00); v01 = gelu_erf(v01);
                v10 = gelu_erf(v10); v11 = gelu_erf(v11);
                __nv_bfloat16 h0 = __float2bfloat16(v00), h1 = __float2bfloat16(v01);
                __nv_bfloat16 l0 = __float2bfloat16(v00 - __bfloat162float(h0));
                __nv_bfloat16 l1 = __float2bfloat16(v01 - __bfloat162float(h1));
                size_t i0 = (size_t)r0 * 256 + (col >> 1);
                reinterpret_cast<__nv_bfloat162*>(outHh)[i0] = __halves2bfloat162(h0, h1);
                reinterpret_cast<__nv_bfloat162*>(outHl)[i0] = __halves2bfloat162(l0, l1);
                h0 = __float2bfloat16(v10); h1 = __float2bfloat16(v11);
                l0 = __float2bfloat16(v10 - __bfloat162float(h0));
                l1 = __float2bfloat16(v11 - __bfloat162float(h1));
                size_t i1 = (size_t)r1 * 256 + (col >> 1);
                reinterpret_cast<__nv_bfloat162*>(outHh)[i1] = __halves2bfloat162(h0, h1);
                reinterpret_cast<__nv_bfloat162*>(outHl)[i1] = __halves2bfloat162(l0, l1);
            } else {
                if (col < Nvalid) {     // Nvalid even -> pair fully valid
                    *(float2*)(outF + (size_t)r0 * Nvalid + col) = make_float2(v00, v01);
                    *(float2*)(outF + (size_t)r1 * Nvalid + col) = make_float2(v10, v11);
                }
            }
        }
    }
}

// ---------------- f32x2 helpers for convs ----------------
__device__ __forceinline__ u64 pack2(float lo, float hi) {
    u64 r; asm("mov.b64 %0, {%1, %2};" : "=l"(r) : "f"(lo), "f"(hi)); return r;
}
__device__ __forceinline__ u64 bcast2(float v) { return pack2(v, v); }
__device__ __forceinline__ void fma2(u64& d, u64 a, u64 b) {
    asm("fma.rn.f32x2 %0, %1, %2, %0;" : "+l"(d) : "l"(a), "l"(b));
}
__device__ __forceinline__ float2 unpack2(u64 d) {
    float2 r; asm("mov.b64 {%0, %1}, %2;" : "=f"(r.x), "=f"(r.y) : "l"(d)); return r;
}

__global__ void pack_w_kernel(const float* __restrict__ w, float2* __restrict__ wp,
                              int COUT, int CIN)
{
    int idx = blockIdx.x * 128 + threadIdx.x;
    int total = (COUT / 2) * CIN * 16;
    if (idx >= total) return;
    int k  = idx & 15;
    int t  = idx >> 4;
    int ic = t % CIN;
    int op = t / CIN;
    float lo = 0.0f, hi = 0.0f;
    if (k < 15) {
        lo = w[((size_t)(2 * op)     * CIN + ic) * 15 + k];
        hi = w[((size_t)(2 * op + 1) * CIN + ic) * 15 + k];
    }
    wp[idx] = make_float2(lo, hi);
}

// ---------------- overlap-add with triangular-fade window ----------------
__global__ void overlap_add_kernel(const float* __restrict__ patches,
                                   float* __restrict__ rec)
{
    int idx = blockIdx.x * 256 + threadIdx.x;
    if (idx >= B_ * C_ * L_) return;
    int l  = idx % L_;
    int bc = idx / L_;
    int c  = bc & (C_ - 1);
    int b  = bc >> 3;

    int i_lo = l - (T_ - 1);
    i_lo = (i_lo > 0) ? (i_lo + STRIDE_ - 1) / STRIDE_ : 0;
    int i_hi = l / STRIDE_;
    if (i_hi > P_ - 1) i_hi = P_ - 1;

    float acc = 0.0f, ws = 0.0f;
    for (int i = i_lo; i <= i_hi; i++) {
        int t = l - i * STRIDE_;
        float w;
        if (t < 50)        w = (float)t * (1.0f / 49.0f);
        else if (t >= 150) w = (float)(199 - t) * (1.0f / 49.0f);
        else               w = 1.0f;
        acc += patches[(((size_t)b * P_ + i) * C_ + c) * T_ + t] * w;
        ws  += w;
    }
    rec[idx] = acc / fmaxf(ws, 1e-8f);
}

// ---------------- conv1d k=15 pad=7, f32x2 ----------------
template<int CIN, int COUT, int OPG, bool DOGELU>
__global__ void __launch_bounds__(128) conv15_f32x2(
    const float* __restrict__ in, const u64* __restrict__ wp,
    const float* __restrict__ bias, float* __restrict__ out)
{
    constexpr int THREADS = 128;
    constexpr int TILE = THREADS * 4;
    constexpr int SROW = TILE + 16;
    __shared__ __align__(16) float sbuf[CIN][SROW];

    const int b     = blockIdx.y;
    const int tile0 = blockIdx.x * TILE;
    const int tid   = threadIdx.x;

    const float* inb = in + (size_t)b * CIN * L_;
    for (int idx = tid; idx < CIN * SROW; idx += THREADS) {
        int ic = idx / SROW, j = idx - ic * SROW;
        int l = tile0 - 7 + j;
        sbuf[ic][j] = (l >= 0 && l < L_) ? inb[(size_t)ic * L_ + l] : 0.0f;
    }
    __syncthreads();

    const int lp = tid * 4;
    const int l0 = tile0 + lp;
    constexpr int NPASS = (COUT / 2) / OPG;

#pragma unroll
    for (int pass = 0; pass < NPASS; pass++) {
        u64 acc[OPG][4];
#pragma unroll
        for (int o = 0; o < OPG; o++) {
            int ch = 2 * (pass * OPG + o);
            u64 bv = pack2(bias[ch], bias[ch + 1]);
            acc[o][0] = bv; acc[o][1] = bv; acc[o][2] = bv; acc[o][3] = bv;
        }
        for (int ic = 0; ic < CIN; ic++) {
            float x[20];
            const float4* xp = reinterpret_cast<const float4*>(&sbuf[ic][lp]);
#pragma unroll
            for (int q = 0; q < 5; q++) {
                float4 v = xp[q];
                x[4*q+0] = v.x; x[4*q+1] = v.y; x[4*q+2] = v.z; x[4*q+3] = v.w;
            }
            u64 xb[18];
#pragma unroll
            for (int j = 0; j < 18; j++) xb[j] = bcast2(x[j]);
#pragma unroll
            for (int o = 0; o < OPG; o++) {
                const ulonglong2* w2 = reinterpret_cast<const ulonglong2*>(
                    wp + ((size_t)(pass * OPG + o) * CIN + ic) * 16);
                u64 wr[16];
#pragma unroll
                for (int q = 0; q < 8; q++) { ulonglong2 t = w2[q]; wr[2*q] = t.x; wr[2*q+1] = t.y; }
#pragma unroll
                for (int k = 0; k < 15; k++) {
                    fma2(acc[o][0], wr[k], xb[k + 0]);
                    fma2(acc[o][1], wr[k], xb[k + 1]);
                    fma2(acc[o][2], wr[k], xb[k + 2]);
                    fma2(acc[o][3], wr[k], xb[k + 3]);
                }
            }
        }
#pragma unroll
        for (int o = 0; o < OPG; o++) {
            int ch = 2 * (pass * OPG + o);
#pragma unroll
            for (int p = 0; p < 4; p++) {
                int l = l0 + p;
                if (l < L_) {
                    float2 v = unpack2(acc[o][p]);
                    if (DOGELU) { v.x = gelu_erf(v.x); v.y = gelu_erf(v.y); }
                    out[((size_t)b * COUT + ch    ) * L_ + l] = v.x;
                    out[((size_t)b * COUT + ch + 1) * L_ + l] = v.y;
                }
            }
        }
    }
}

// ---------------- conv3 + residual + pointwise, fused ----------------
__global__ void __launch_bounds__(128) conv3_res_pw_f32x2(
    const float* __restrict__ in, const u64* __restrict__ wp,
    const float* __restrict__ bias, const float* __restrict__ rec,
    const float* __restrict__ pw, const float* __restrict__ pb,
    float* __restrict__ out)
{
    constexpr int CIN = 16, THREADS = 128, TILE = THREADS * 4, SROW = TILE + 16;
    __shared__ __align__(16) float sbuf[CIN][SROW];

    const int b     = blockIdx.y;
    const int tile0 = blockIdx.x * TILE;
    const int tid   = threadIdx.x;

    const float* inb = in + (size_t)b * CIN * L_;
    for (int idx = tid; idx < CIN * SROW; idx += THREADS) {
        int ic = idx / SROW, j = idx - ic * SROW;
        int l = tile0 - 7 + j;
        sbuf[ic][j] = (l >= 0 && l < L_) ? inb[(size_t)ic * L_ + l] : 0.0f;
    }
    __syncthreads();

    const int lp = tid * 4;
    const int l0 = tile0 + lp;

    u64 acc[4][4];
#pragma unroll
    for (int o = 0; o < 4; o++) {
        u64 bv = pack2(bias[2*o], bias[2*o + 1]);
        acc[o][0] = bv; acc[o][1] = bv; acc[o][2] = bv; acc[o][3] = bv;
    }
    for (int ic = 0; ic < CIN; ic++) {
        float x[20];
        const float4* xp = reinterpret_cast<const float4*>(&sbuf[ic][lp]);
#pragma unroll
        for (int q = 0; q < 5; q++) {
            float4 v = xp[q];
            x[4*q+0] = v.x; x[4*q+1] = v.y; x[4*q+2] = v.z; x[4*q+3] = v.w;
        }
        u64 xb[18];
#pragma unroll
        for (int j = 0; j < 18; j++) xb[j] = bcast2(x[j]);
#pragma unroll
        for (int o = 0; o < 4; o++) {
            const ulonglong2* w2 = reinterpret_cast<const ulonglong2*>(
                wp + ((size_t)o * CIN + ic) * 16);
            u64 wr[16];
#pragma unroll
            for (int q = 0; q < 8; q++) { ulonglong2 t = w2[q]; wr[2*q] = t.x; wr[2*q+1] = t.y; }
#pragma unroll
            for (int k = 0; k < 15; k++) {
                fma2(acc[o][0], wr[k], xb[k + 0]);
                fma2(acc[o][1], wr[k], xb[k + 1]);
                fma2(acc[o][2], wr[k], xb[k + 2]);
                fma2(acc[o][3], wr[k], xb[k + 3]);
            }
        }
    }

    float recf[8][4];
#pragma unroll
    for (int o = 0; o < 4; o++)
#pragma unroll
        for (int p = 0; p < 4; p++) {
            int l = l0 + p;
            float2 v = unpack2(acc[o][p]);
            if (l < L_) {
                recf[2*o    ][p] = rec[((size_t)b * C_ + 2*o    ) * L_ + l] + v.x;
                recf[2*o + 1][p] = rec[((size_t)b * C_ + 2*o + 1) * L_ + l] + v.y;
            } else {
                recf[2*o][p] = 0.0f; recf[2*o + 1][p] = 0.0f;
            }
        }

#pragma unroll
    for (int o = 0; o < 8; o++) {
        float r0 = pb[o], r1 = r0, r2 = r0, r3 = r0;
#pragma unroll
        for (int c = 0; c < 8; c++) {
            float wv = __ldg(&pw[o * C_ + c]);
            r0 += wv * recf[c][0];
            r1 += wv * recf[c][1];
            r2 += wv * recf[c][2];
            r3 += wv * recf[c][3];
        }
        size_t base = ((size_t)b * C_ + o) * L_;
        if (l0 + 0 < L_) out[base + l0 + 0] = r0;
        if (l0 + 1 < L_) out[base + l0 + 1] = r1;
        if (l0 + 2 < L_) out[base + l0 + 2] = r2;
        if (l0 + 3 < L_) out[base + l0 + 3] = r3;
    }
}

// ---------------- launcher ----------------
extern "C" void kernel_launch(void* const* d_in, const int* in_sizes, int n_in,
                              void* d_out, int out_size)
{
    const float* X   = (const float*)d_in[0];
    const float* W1  = (const float*)d_in[1];
    const float* b1  = (const float*)d_in[2];
    const float* W2  = (const float*)d_in[3];
    const float* b2  = (const float*)d_in[4];
    const float* rw1 = (const float*)d_in[5];
    const float* rb1 = (const float*)d_in[6];
    const float* rw2 = (const float*)d_in[7];
    const float* rb2 = (const float*)d_in[8];
    const float* rw3 = (const float*)d_in[9];
    const float* rb3 = (const float*)d_in[10];
    const float* pw  = (const float*)d_in[11];
    const float* pb  = (const float*)d_in[12];
    float* out = (float*)d_out;

    __nv_bfloat16 *pXh, *pXl, *pHh, *pHl, *pW1th, *pW1tl, *pW2th, *pW2tl;
    float *pPatches, *pRec, *pR1, *pR2;
    u64 *pWp1, *pWp2, *pWp3;
    cudaGetSymbolAddress((void**)&pXh,   g_Xh);
    cudaGetSymbolAddress((void**)&pXl,   g_Xl);
    cudaGetSymbolAddress((void**)&pHh,   g_Hh);
    cudaGetSymbolAddress((void**)&pHl,   g_Hl);
    cudaGetSymbolAddress((void**)&pW1th, g_W1th);
    cudaGetSymbolAddress((void**)&pW1tl, g_W1tl);
    cudaGetSymbolAddress((void**)&pW2th, g_W2th);
    cudaGetSymbolAddress((void**)&pW2tl, g_W2tl);
    cudaGetSymbolAddress((void**)&pPatches, g_patches);
    cudaGetSymbolAddress((void**)&pRec,  g_rec);
    cudaGetSymbolAddress((void**)&pR1,   g_r1);
    cudaGetSymbolAddress((void**)&pR2,   g_r2);
    cudaGetSymbolAddress((void**)&pWp1,  g_wp1);
    cudaGetSymbolAddress((void**)&pWp2,  g_wp2);
    cudaGetSymbolAddress((void**)&pWp3,  g_wp3);

    // 0) preps
    pack_w_kernel<<<(16*8*16  + 127) / 128, 128>>>(rw1, (float2*)pWp1, 32, 8);
    pack_w_kernel<<<(8*32*16  + 127) / 128, 128>>>(rw2, (float2*)pWp2, 16, 32);
    pack_w_kernel<<<(4*16*16  + 127) / 128, 128>>>(rw3, (float2*)pWp3, 8, 16);
    {
        int n4 = (int)((size_t)M_ * 512 / 4);
        split_f32_kernel<<<(n4 + 255) / 256, 256>>>(X, pXh, pXl, n4);
    }
    transp_split_kernel<<<(512*512 + 255) / 256, 256>>>(W1, pW1th, pW1tl, 512, 512, 512);
    transp_split_kernel<<<(256*512 + 255) / 256, 256>>>(W2, pW2th, pW2tl, 512, 200, 256);

    // 1) Hh/Hl = split(GELU(X @ W1 + b1))   (HMMA)
    gemm_hmma<true><<<dim3(8, M_ / 128), 256>>>(
        pXh, pXl, pW1th, pW1tl, b1, 512, pHh, pHl, nullptr);

    // 2) patches = H @ W2 + b2   (HMMA)
    gemm_hmma<false><<<dim3(4, M_ / 128), 256>>>(
        pHh, pHl, pW2th, pW2tl, b2, 200, nullptr, nullptr, pPatches);

    // 3) overlap-add -> rec
    {
        int total = B_ * C_ * L_;
        overlap_add_kernel<<<(total + 255) / 256, 256>>>(pPatches, pRec);
    }
    // 4) r1 = GELU(conv1(rec))   8 -> 32
    {
        dim3 grid((L_ + 511) / 512, B_);
        conv15_f32x2<8, 32, 4, true><<<grid, 128>>>(pRec, pWp1, rb1, pR1);
    }
    // 5) r2 = GELU(conv2(r1))    32 -> 16
    {
        dim3 grid((L_ + 511) / 512, B_);
        conv15_f32x2<32, 16, 4, true><<<grid, 128>>>(pR1, pWp2, rb2, pR2);
    }
    // 6) out = pw @ (rec + conv3(r2)) + pb
    {
        dim3 grid((L_ + 511) / 512, B_);
        conv3_res_pw_f32x2<<<grid, 128>>>(pR2, pWp3, rb3, pRec, pw, pb, out);
    }
}

// round 6
// speedup vs baseline: 2.8305x; 1.1183x over previous
#include <cuda_runtime.h>
#include <cuda_bf16.h>
#include <math.h>
#include <stdint.h>

#define B_      1024
#define P_      11
#define C_      8
#define H_      512
#define T_      200
#define L_      2000
#define STRIDE_ 180
#define M_      (B_*P_*C_)   // 90112 rows for the per-patch MLP

typedef unsigned long long u64;
typedef unsigned int u32;

// ---------------- scratch (device globals; no allocation allowed) ----------------
__device__ __nv_bfloat16 g_Xh[(size_t)M_ * 512];
__device__ __nv_bfloat16 g_Xl[(size_t)M_ * 512];
__device__ __nv_bfloat16 g_Hh[(size_t)M_ * 512];
__device__ __nv_bfloat16 g_Hl[(size_t)M_ * 512];
__device__ __nv_bfloat16 g_W1th[512 * 512];
__device__ __nv_bfloat16 g_W1tl[512 * 512];
__device__ __nv_bfloat16 g_W2th[256 * 512];
__device__ __nv_bfloat16 g_W2tl[256 * 512];
__device__ float g_patches[(size_t)M_ * T_];
__device__ float g_rec[(size_t)B_ * C_ * L_];
__device__ __nv_bfloat16 g_r1h[(size_t)B_ * 32 * L_];  // conv1 out hi (ch-major)
__device__ __nv_bfloat16 g_r1l[(size_t)B_ * 32 * L_];  // conv1 out lo
__device__ float g_r2[(size_t)B_ * 2*C_ * L_];
// packed conv weights (f32x2) for conv1 / conv3
__device__ u64 g_wp1[16 * 8  * 16];
__device__ u64 g_wp3[4  * 16 * 16];
// conv2 weights as bf16 split, [co=16][K=480], K ordered (k outer, ic inner)
__device__ __nv_bfloat16 g_w2h[16 * 480];
__device__ __nv_bfloat16 g_w2l[16 * 480];

__device__ __forceinline__ float gelu_erf(float x) {
    return 0.5f * x * (1.0f + erff(x * 0.7071067811865476f));
}

// ---------------- warp MMA primitives (target-portable PTX) ----------------
__device__ __forceinline__ uint32_t smem_u32(const void* p) {
    uint32_t a;
    asm("{ .reg .u64 t; cvta.to.shared.u64 t, %1; cvt.u32.u64 %0, t; }" : "=r"(a) : "l"(p));
    return a;
}
__device__ __forceinline__ void ldsm_x4(u32& r0, u32& r1, u32& r2, u32& r3, u32 addr) {
    asm volatile("ldmatrix.sync.aligned.m8n8.x4.shared.b16 {%0,%1,%2,%3}, [%4];"
        : "=r"(r0), "=r"(r1), "=r"(r2), "=r"(r3) : "r"(addr));
}
__device__ __forceinline__ void mma_bf16(float* d, const u32* a, const u32* b) {
    asm volatile("mma.sync.aligned.m16n8k16.row.col.f32.bf16.bf16.f32 "
        "{%0,%1,%2,%3}, {%4,%5,%6,%7}, {%8,%9}, {%0,%1,%2,%3};"
        : "+f"(d[0]), "+f"(d[1]), "+f"(d[2]), "+f"(d[3])
        : "r"(a[0]), "r"(a[1]), "r"(a[2]), "r"(a[3]), "r"(b[0]), "r"(b[1]));
}

// ================= prep kernels =================
__global__ void split_f32_kernel(const float* __restrict__ x,
                                 __nv_bfloat16* __restrict__ hh,
                                 __nv_bfloat16* __restrict__ hl, int n4)
{
    int i = blockIdx.x * 256 + threadIdx.x;
    if (i >= n4) return;
    float4 v = reinterpret_cast<const float4*>(x)[i];
    float f[4] = {v.x, v.y, v.z, v.w};
    __nv_bfloat16 h[4], l[4];
#pragma unroll
    for (int j = 0; j < 4; j++) {
        h[j] = __float2bfloat16(f[j]);
        l[j] = __float2bfloat16(f[j] - __bfloat162float(h[j]));
    }
    __nv_bfloat162* ph = reinterpret_cast<__nv_bfloat162*>(hh) + 2 * (size_t)i;
    __nv_bfloat162* pl = reinterpret_cast<__nv_bfloat162*>(hl) + 2 * (size_t)i;
    ph[0] = __halves2bfloat162(h[0], h[1]); ph[1] = __halves2bfloat162(h[2], h[3]);
    pl[0] = __halves2bfloat162(l[0], l[1]); pl[1] = __halves2bfloat162(l[2], l[3]);
}

__global__ void transp_split_kernel(const float* __restrict__ W,
                                    __nv_bfloat16* __restrict__ th,
                                    __nv_bfloat16* __restrict__ tl,
                                    int Kdim, int Nsrc, int Npad)
{
    int idx = blockIdx.x * 256 + threadIdx.x;
    if (idx >= Npad * Kdim) return;
    int n = idx / Kdim, k = idx - n * Kdim;
    float f = (n < Nsrc) ? W[(size_t)k * Nsrc + n] : 0.0f;
    __nv_bfloat16 h = __float2bfloat16(f);
    th[idx] = h;
    tl[idx] = __float2bfloat16(f - __bfloat162float(h));
}

// rw2 (16,32,15) fp32 -> [co][k*32+ic] bf16 hi/lo
__global__ void w2_prep_kernel(const float* __restrict__ w,
                               __nv_bfloat16* __restrict__ wh,
                               __nv_bfloat16* __restrict__ wl)
{
    int idx = blockIdx.x * 256 + threadIdx.x;
    if (idx >= 16 * 480) return;
    int co = idx / 480, c = idx - co * 480;
    int k = c >> 5, ic = c & 31;
    float f = w[((size_t)co * 32 + ic) * 15 + k];
    __nv_bfloat16 h = __float2bfloat16(f);
    wh[idx] = h;
    wl[idx] = __float2bfloat16(f - __bfloat162float(h));
}

// ================= HMMA GEMM (mma.sync bf16, 3-way split) =================
#define ASTR 40

template<bool GELU_SPLIT>
__global__ void __launch_bounds__(256, 2) gemm_hmma(
    const __nv_bfloat16* __restrict__ Ah, const __nv_bfloat16* __restrict__ Al,
    const __nv_bfloat16* __restrict__ Bh, const __nv_bfloat16* __restrict__ Bl,
    const float* __restrict__ bias, int Nvalid,
    __nv_bfloat16* __restrict__ outHh, __nv_bfloat16* __restrict__ outHl,
    float* __restrict__ outF)
{
    __shared__ __align__(16) __nv_bfloat16 sAh[128 * ASTR];
    __shared__ __align__(16) __nv_bfloat16 sAl[128 * ASTR];
    __shared__ __align__(16) __nv_bfloat16 sBh[64 * ASTR];
    __shared__ __align__(16) __nv_bfloat16 sBl[64 * ASTR];

    const int tid  = threadIdx.x;
    const int lane = tid & 31;
    const int wid  = tid >> 5;
    const int wm   = wid & 3;
    const int wn   = wid >> 2;
    const int bm   = blockIdx.y * 128;
    const int bn   = blockIdx.x * 64;

    float acc[2][4][4];
#pragma unroll
    for (int i = 0; i < 2; i++)
#pragma unroll
        for (int j = 0; j < 4; j++)
#pragma unroll
            for (int q = 0; q < 4; q++) acc[i][j][q] = 0.0f;

    const int ar = tid >> 2;
    const int aq = (tid & 3) * 8;
    const size_t gA0 = (size_t)(bm + ar) * 512 + aq;
    const size_t gA1 = (size_t)(bm + ar + 64) * 512 + aq;
    const size_t gB0 = (size_t)(bn + ar) * 512 + aq;

    const u32 sbAh = smem_u32(sAh), sbAl = smem_u32(sAl);
    const u32 sbBh = smem_u32(sBh), sbBl = smem_u32(sBl);

    const int lrow = lane & 15;
    const int lhalf = (lane >> 4) * 8;
    const u32 aoffA0 = ((wm * 32 +      lrow) * ASTR + lhalf) * 2;
    const u32 aoffA1 = ((wm * 32 + 16 + lrow) * ASTR + lhalf) * 2;
    const u32 aoffB0 = ((wn * 32 +      lrow) * ASTR + lhalf) * 2;
    const u32 aoffB1 = ((wn * 32 + 16 + lrow) * ASTR + lhalf) * 2;

    uint4 pah0, pah1, pal0, pal1, pbh, pbl;
    pah0 = *(const uint4*)(Ah + gA0); pah1 = *(const uint4*)(Ah + gA1);
    pal0 = *(const uint4*)(Al + gA0); pal1 = *(const uint4*)(Al + gA1);
    pbh  = *(const uint4*)(Bh + gB0); pbl  = *(const uint4*)(Bl + gB0);

    const int sA0 = ar * ASTR + aq, sA1 = (ar + 64) * ASTR + aq, sB0 = ar * ASTR + aq;

    for (int kt = 0; kt < 16; kt++) {
        *(uint4*)(sAh + sA0) = pah0; *(uint4*)(sAh + sA1) = pah1;
        *(uint4*)(sAl + sA0) = pal0; *(uint4*)(sAl + sA1) = pal1;
        *(uint4*)(sBh + sB0) = pbh;  *(uint4*)(sBl + sB0) = pbl;
        __syncthreads();

        if (kt < 15) {
            int k0 = (kt + 1) * 32;
            pah0 = *(const uint4*)(Ah + gA0 + k0); pah1 = *(const uint4*)(Ah + gA1 + k0);
            pal0 = *(const uint4*)(Al + gA0 + k0); pal1 = *(const uint4*)(Al + gA1 + k0);
            pbh  = *(const uint4*)(Bh + gB0 + k0); pbl  = *(const uint4*)(Bl + gB0 + k0);
        }

#pragma unroll
        for (int kk = 0; kk < 2; kk++) {
            const u32 kadd = kk * 32;
            u32 a_h[2][4], a_l[2][4];
            ldsm_x4(a_h[0][0], a_h[0][1], a_h[0][2], a_h[0][3], sbAh + aoffA0 + kadd);
            ldsm_x4(a_h[1][0], a_h[1][1], a_h[1][2], a_h[1][3], sbAh + aoffA1 + kadd);
            ldsm_x4(a_l[0][0], a_l[0][1], a_l[0][2], a_l[0][3], sbAl + aoffA0 + kadd);
            ldsm_x4(a_l[1][0], a_l[1][1], a_l[1][2], a_l[1][3], sbAl + aoffA1 + kadd);

            u32 t0, t1, t2, t3;
            u32 b_h[4][2], b_l[4][2];
            ldsm_x4(t0, t1, t2, t3, sbBh + aoffB0 + kadd);
            b_h[0][0] = t0; b_h[0][1] = t2; b_h[1][0] = t1; b_h[1][1] = t3;
            ldsm_x4(t0, t1, t2, t3, sbBh + aoffB1 + kadd);
            b_h[2][0] = t0; b_h[2][1] = t2; b_h[3][0] = t1; b_h[3][1] = t3;
            ldsm_x4(t0, t1, t2, t3, sbBl + aoffB0 + kadd);
            b_l[0][0] = t0; b_l[0][1] = t2; b_l[1][0] = t1; b_l[1][1] = t3;
            ldsm_x4(t0, t1, t2, t3, sbBl + aoffB1 + kadd);
            b_l[2][0] = t0; b_l[2][1] = t2; b_l[3][0] = t1; b_l[3][1] = t3;

#pragma unroll
            for (int mi = 0; mi < 2; mi++)
#pragma unroll
                for (int ni = 0; ni < 4; ni++) {
                    mma_bf16(acc[mi][ni], a_h[mi], b_h[ni]);
                    mma_bf16(acc[mi][ni], a_h[mi], b_l[ni]);
                    mma_bf16(acc[mi][ni], a_l[mi], b_h[ni]);
                }
        }
        __syncthreads();
    }

    const int grp = lane >> 2;
    const int qc  = (lane & 3) * 2;
#pragma unroll
    for (int mi = 0; mi < 2; mi++) {
        const int r0 = bm + wm * 32 + mi * 16 + grp;
        const int r1 = r0 + 8;
#pragma unroll
        for (int ni = 0; ni < 4; ni++) {
            const int col = bn + wn * 32 + ni * 8 + qc;
            float bv0 = __ldg(&bias[col]), bv1 = __ldg(&bias[col + 1]);
            float v00 = acc[mi][ni][0] + bv0, v01 = acc[mi][ni][1] + bv1;
            float v10 = acc[mi][ni][2] + bv0, v11 = acc[mi][ni][3] + bv1;
            if (GELU_SPLIT) {
                v00 = gelu_erf(v00); v01 = gelu_erf(v01);
                v10 = gelu_erf(v10); v11 = gelu_erf(v11);
                __nv_bfloat16 h0 = __float2bfloat16(v00), h1 = __float2bfloat16(v01);
                __nv_bfloat16 l0 = __float2bfloat16(v00 - __bfloat162float(h0));
                __nv_bfloat16 l1 = __float2bfloat16(v01 - __bfloat162float(h1));
                size_t i0 = (size_t)r0 * 256 + (col >> 1);
                reinterpret_cast<__nv_bfloat162*>(outHh)[i0] = __halves2bfloat162(h0, h1);
                reinterpret_cast<__nv_bfloat162*>(outHl)[i0] = __halves2bfloat162(l0, l1);
                h0 = __float2bfloat16(v10); h1 = __float2bfloat16(v11);
                l0 = __float2bfloat16(v10 - __bfloat162float(h0));
                l1 = __float2bfloat16(v11 - __bfloat162float(h1));
                size_t i1 = (size_t)r1 * 256 + (col >> 1);
                reinterpret_cast<__nv_bfloat162*>(outHh)[i1] = __halves2bfloat162(h0, h1);
                reinterpret_cast<__nv_bfloat162*>(outHl)[i1] = __halves2bfloat162(l0, l1);
            } else {
                if (col < Nvalid) {
                    *(float2*)(outF + (size_t)r0 * Nvalid + col) = make_float2(v00, v01);
                    *(float2*)(outF + (size_t)r1 * Nvalid + col) = make_float2(v10, v11);
                }
            }
        }
    }
}

// ---------------- f32x2 helpers ----------------
__device__ __forceinline__ u64 pack2(float lo, float hi) {
    u64 r; asm("mov.b64 %0, {%1, %2};" : "=l"(r) : "f"(lo), "f"(hi)); return r;
}
__device__ __forceinline__ u64 bcast2(float v) { return pack2(v, v); }
__device__ __forceinline__ void fma2(u64& d, u64 a, u64 b) {
    asm("fma.rn.f32x2 %0, %1, %2, %0;" : "+l"(d) : "l"(a), "l"(b));
}
__device__ __forceinline__ float2 unpack2(u64 d) {
    float2 r; asm("mov.b64 {%0, %1}, %2;" : "=f"(r.x), "=f"(r.y) : "l"(d)); return r;
}

__global__ void pack_w_kernel(const float* __restrict__ w, float2* __restrict__ wp,
                              int COUT, int CIN)
{
    int idx = blockIdx.x * 128 + threadIdx.x;
    int total = (COUT / 2) * CIN * 16;
    if (idx >= total) return;
    int k  = idx & 15;
    int t  = idx >> 4;
    int ic = t % CIN;
    int op = t / CIN;
    float lo = 0.0f, hi = 0.0f;
    if (k < 15) {
        lo = w[((size_t)(2 * op)     * CIN + ic) * 15 + k];
        hi = w[((size_t)(2 * op + 1) * CIN + ic) * 15 + k];
    }
    wp[idx] = make_float2(lo, hi);
}

// ---------------- overlap-add ----------------
__global__ void overlap_add_kernel(const float* __restrict__ patches,
                                   float* __restrict__ rec)
{
    int idx = blockIdx.x * 256 + threadIdx.x;
    if (idx >= B_ * C_ * L_) return;
    int l  = idx % L_;
    int bc = idx / L_;
    int c  = bc & (C_ - 1);
    int b  = bc >> 3;

    int i_lo = l - (T_ - 1);
    i_lo = (i_lo > 0) ? (i_lo + STRIDE_ - 1) / STRIDE_ : 0;
    int i_hi = l / STRIDE_;
    if (i_hi > P_ - 1) i_hi = P_ - 1;

    float acc = 0.0f, ws = 0.0f;
    for (int i = i_lo; i <= i_hi; i++) {
        int t = l - i * STRIDE_;
        float w;
        if (t < 50)        w = (float)t * (1.0f / 49.0f);
        else if (t >= 150) w = (float)(199 - t) * (1.0f / 49.0f);
        else               w = 1.0f;
        acc += patches[(((size_t)b * P_ + i) * C_ + c) * T_ + t] * w;
        ws  += w;
    }
    rec[idx] = acc / fmaxf(ws, 1e-8f);
}

// ---------------- conv1: 8->32 k15, f32x2 compute, bf16-split output ----------------
// output layout [b][ch=32][l] bf16 hi/lo. 128 thr, 4 positions each (TILE=512).
__global__ void __launch_bounds__(128) conv1_f32x2_bf16(
    const float* __restrict__ in, const u64* __restrict__ wp,
    const float* __restrict__ bias,
    __nv_bfloat16* __restrict__ outh, __nv_bfloat16* __restrict__ outl)
{
    constexpr int CIN = 8, THREADS = 128, TILE = 512, SROW = TILE + 16;
    __shared__ __align__(16) float sbuf[CIN][SROW];

    const int b     = blockIdx.y;
    const int tile0 = blockIdx.x * TILE;
    const int tid   = threadIdx.x;

    const float* inb = in + (size_t)b * CIN * L_;
    for (int idx = tid; idx < CIN * SROW; idx += THREADS) {
        int ic = idx / SROW, j = idx - ic * SROW;
        int l = tile0 - 7 + j;
        sbuf[ic][j] = (l >= 0 && l < L_) ? inb[(size_t)ic * L_ + l] : 0.0f;
    }
    __syncthreads();

    const int lp = tid * 4;
    const int l0 = tile0 + lp;
    const bool valid = (l0 < L_);   // L%4==0 -> all-or-nothing per thread

#pragma unroll
    for (int pass = 0; pass < 4; pass++) {
        u64 acc[4][4];
#pragma unroll
        for (int o = 0; o < 4; o++) {
            int ch = 2 * (pass * 4 + o);
            u64 bv = pack2(bias[ch], bias[ch + 1]);
            acc[o][0] = bv; acc[o][1] = bv; acc[o][2] = bv; acc[o][3] = bv;
        }
        for (int ic = 0; ic < CIN; ic++) {
            float x[20];
            const float4* xp = reinterpret_cast<const float4*>(&sbuf[ic][lp]);
#pragma unroll
            for (int q = 0; q < 5; q++) {
                float4 v = xp[q];
                x[4*q+0] = v.x; x[4*q+1] = v.y; x[4*q+2] = v.z; x[4*q+3] = v.w;
            }
            u64 xb[18];
#pragma unroll
            for (int j = 0; j < 18; j++) xb[j] = bcast2(x[j]);
#pragma unroll
            for (int o = 0; o < 4; o++) {
                const ulonglong2* w2 = reinterpret_cast<const ulonglong2*>(
                    wp + ((size_t)(pass * 4 + o) * CIN + ic) * 16);
                u64 wr[16];
#pragma unroll
                for (int q = 0; q < 8; q++) { ulonglong2 t = w2[q]; wr[2*q] = t.x; wr[2*q+1] = t.y; }
#pragma unroll
                for (int k = 0; k < 15; k++) {
                    fma2(acc[o][0], wr[k], xb[k + 0]);
                    fma2(acc[o][1], wr[k], xb[k + 1]);
                    fma2(acc[o][2], wr[k], xb[k + 2]);
                    fma2(acc[o][3], wr[k], xb[k + 3]);
                }
            }
        }
        if (valid) {
#pragma unroll
            for (int o = 0; o < 4; o++) {
                int ch0 = 2 * (pass * 4 + o), ch1 = ch0 + 1;
                float vx[4], vy[4];
#pragma unroll
                for (int p = 0; p < 4; p++) {
                    float2 v = unpack2(acc[o][p]);
                    vx[p] = gelu_erf(v.x); vy[p] = gelu_erf(v.y);
                }
                // channel ch0: 4 consecutive positions, bf16 hi+lo
                __nv_bfloat16 h[4], l[4];
#pragma unroll
                for (int p = 0; p < 4; p++) {
                    h[p] = __float2bfloat16(vx[p]);
                    l[p] = __float2bfloat16(vx[p] - __bfloat162float(h[p]));
                }
                __nv_bfloat162 hp0 = __halves2bfloat162(h[0], h[1]);
                __nv_bfloat162 hp1 = __halves2bfloat162(h[2], h[3]);
                __nv_bfloat162 lp0 = __halves2bfloat162(l[0], l[1]);
                __nv_bfloat162 lp1 = __halves2bfloat162(l[2], l[3]);
                size_t eidx = ((size_t)b * 32 + ch0) * L_ + l0;
                *(uint2*)(outh + eidx) = make_uint2(*(u32*)&hp0, *(u32*)&hp1);
                *(uint2*)(outl + eidx) = make_uint2(*(u32*)&lp0, *(u32*)&lp1);
                // channel ch1
#pragma unroll
                for (int p = 0; p < 4; p++) {
                    h[p] = __float2bfloat16(vy[p]);
                    l[p] = __float2bfloat16(vy[p] - __bfloat162float(h[p]));
                }
                hp0 = __halves2bfloat162(h[0], h[1]);
                hp1 = __halves2bfloat162(h[2], h[3]);
                lp0 = __halves2bfloat162(l[0], l[1]);
                lp1 = __halves2bfloat162(l[2], l[3]);
                eidx = ((size_t)b * 32 + ch1) * L_ + l0;
                *(uint2*)(outh + eidx) = make_uint2(*(u32*)&hp0, *(u32*)&hp1);
                *(uint2*)(outl + eidx) = make_uint2(*(u32*)&lp0, *(u32*)&lp1);
            }
        }
    }
}

// ---------------- conv2: 32->16 k15 as implicit-GEMM HMMA ----------------
// M = 128 positions/block, N = 16 out ch, K = 480 (k outer, ic inner).
// A fragment for tap k = ldmatrix at smem row (pos + k); X smem is [row][ic].
#define X2STR 40    // bf16 per X row (32 + 8 pad) -> conflict-free ldmatrix
#define W2STR 488   // bf16 per W row (480 + 8 pad)

__global__ void __launch_bounds__(256) conv2_hmma(
    const __nv_bfloat16* __restrict__ r1h, const __nv_bfloat16* __restrict__ r1l,
    const __nv_bfloat16* __restrict__ wh, const __nv_bfloat16* __restrict__ wl,
    const float* __restrict__ bias, float* __restrict__ out)
{
    __shared__ __align__(16) __nv_bfloat16 sXh[144 * X2STR];
    __shared__ __align__(16) __nv_bfloat16 sXl[144 * X2STR];
    __shared__ __align__(16) __nv_bfloat16 sWh[16 * W2STR];
    __shared__ __align__(16) __nv_bfloat16 sWl[16 * W2STR];
    __shared__ float sOut[128 * 17];

    const int tid  = threadIdx.x;
    const int lane = tid & 31;
    const int wm   = tid >> 5;          // 8 warps, m16 each
    const int b    = blockIdx.y;
    const int t0   = blockIdx.x * 128;  // output position base

    // load weights (hi/lo), [16][480] -> padded rows
    for (int i = tid; i < 16 * 240; i += 256) {
        int r = i / 240, c = i - r * 240;
        ((u32*)sWh)[r * (W2STR/2) + c] = ((const u32*)wh)[r * 240 + c];
        ((u32*)sWl)[r * (W2STR/2) + c] = ((const u32*)wl)[r * 240 + c];
    }
    // load X tile with halo, transposing [ch][l] -> [row][ic]
    // rows 0..143 <-> gp = t0 + row - 8; taps use rows (p + k + 1)
    for (int i = tid; i < 32 * 72; i += 256) {
        int ch = i / 72, rp = i - ch * 72;
        int gp0 = t0 + 2 * rp - 8;
        u32 vh = 0, vl = 0;
        if (gp0 >= 0 && gp0 + 1 < L_) {
            size_t ui = (((size_t)b * 32 + ch) * L_ + gp0) >> 1;
            vh = ((const u32*)r1h)[ui];
            vl = ((const u32*)r1l)[ui];
        }
        int r0 = 2 * rp;
        sXh[r0 * X2STR + ch]       = __ushort_as_bfloat16((unsigned short)(vh & 0xFFFF));
        sXh[(r0 + 1) * X2STR + ch] = __ushort_as_bfloat16((unsigned short)(vh >> 16));
        sXl[r0 * X2STR + ch]       = __ushort_as_bfloat16((unsigned short)(vl & 0xFFFF));
        sXl[(r0 + 1) * X2STR + ch] = __ushort_as_bfloat16((unsigned short)(vl >> 16));
    }
    __syncthreads();

    const u32 sbXh = smem_u32(sXh), sbXl = smem_u32(sXl);
    const u32 sbWh = smem_u32(sWh), sbWl = smem_u32(sWl);

    float acc[2][4];
#pragma unroll
    for (int ni = 0; ni < 2; ni++)
#pragma unroll
        for (int q = 0; q < 4; q++) acc[ni][q] = 0.0f;

    const int lrow = lane & 15;
    const int lhalf = (lane >> 4) * 8;
    const u32 boff = sbWh + ((lane & 15) * W2STR + lhalf) * 2;       // hi W base
    const u32 boffl = sbWl + ((lane & 15) * W2STR + lhalf) * 2;

#pragma unroll 2
    for (int ks = 0; ks < 30; ks++) {
        const int k   = ks >> 1;
        const int icb = (ks & 1) * 16;
        const u32 arow = wm * 16 + lrow + k + 1;
        const u32 aadd = (arow * X2STR + icb + lhalf) * 2;

        u32 ah[4], al[4];
        ldsm_x4(ah[0], ah[1], ah[2], ah[3], sbXh + aadd);
        ldsm_x4(al[0], al[1], al[2], al[3], sbXl + aadd);

        u32 t0r, t1r, t2r, t3r;
        u32 bh[2][2], bl[2][2];
        ldsm_x4(t0r, t1r, t2r, t3r, boff + ks * 32);
        bh[0][0] = t0r; bh[0][1] = t2r; bh[1][0] = t1r; bh[1][1] = t3r;
        ldsm_x4(t0r, t1r, t2r, t3r, boffl + ks * 32);
        bl[0][0] = t0r; bl[0][1] = t2r; bl[1][0] = t1r; bl[1][1] = t3r;

#pragma unroll
        for (int ni = 0; ni < 2; ni++) {
            mma_bf16(acc[ni], ah, bh[ni]);
            mma_bf16(acc[ni], ah, bl[ni]);
            mma_bf16(acc[ni], al, bh[ni]);
        }
    }

    // epilogue: bias + gelu -> sOut[p][ch] -> coalesced [ch][l] store
    const int grp = lane >> 2;
    const int qc  = (lane & 3) * 2;
#pragma unroll
    for (int ni = 0; ni < 2; ni++) {
        int ch = ni * 8 + qc;
        float bv0 = __ldg(&bias[ch]), bv1 = __ldg(&bias[ch + 1]);
        int p0 = wm * 16 + grp, p1 = p0 + 8;
        sOut[p0 * 17 + ch]     = gelu_erf(acc[ni][0] + bv0);
        sOut[p0 * 17 + ch + 1] = gelu_erf(acc[ni][1] + bv1);
        sOut[p1 * 17 + ch]     = gelu_erf(acc[ni][2] + bv0);
        sOut[p1 * 17 + ch + 1] = gelu_erf(acc[ni][3] + bv1);
    }
    __syncthreads();
    for (int i = tid; i < 16 * 128; i += 256) {
        int ch = i >> 7, l = i & 127;
        if (t0 + l < L_)
            out[((size_t)b * 16 + ch) * L_ + t0 + l] = sOut[l * 17 + ch];
    }
}

// ---------------- conv3 + residual + pointwise, fused, f32x2 ----------------
__global__ void __launch_bounds__(128) conv3_res_pw_f32x2(
    const float* __restrict__ in, const u64* __restrict__ wp,
    const float* __restrict__ bias, const float* __restrict__ rec,
    const float* __restrict__ pw, const float* __restrict__ pb,
    float* __restrict__ out)
{
    constexpr int CIN = 16, THREADS = 128, TILE = THREADS * 4, SROW = TILE + 16;
    __shared__ __align__(16) float sbuf[CIN][SROW];

    const int b     = blockIdx.y;
    const int tile0 = blockIdx.x * TILE;
    const int tid   = threadIdx.x;

    const float* inb = in + (size_t)b * CIN * L_;
    for (int idx = tid; idx < CIN * SROW; idx += THREADS) {
        int ic = idx / SROW, j = idx - ic * SROW;
        int l = tile0 - 7 + j;
        sbuf[ic][j] = (l >= 0 && l < L_) ? inb[(size_t)ic * L_ + l] : 0.0f;
    }
    __syncthreads();

    const int lp = tid * 4;
    const int l0 = tile0 + lp;

    u64 acc[4][4];
#pragma unroll
    for (int o = 0; o < 4; o++) {
        u64 bv = pack2(bias[2*o], bias[2*o + 1]);
        acc[o][0] = bv; acc[o][1] = bv; acc[o][2] = bv; acc[o][3] = bv;
    }
    for (int ic = 0; ic < CIN; ic++) {
        float x[20];
        const float4* xp = reinterpret_cast<const float4*>(&sbuf[ic][lp]);
#pragma unroll
        for (int q = 0; q < 5; q++) {
            float4 v = xp[q];
            x[4*q+0] = v.x; x[4*q+1] = v.y; x[4*q+2] = v.z; x[4*q+3] = v.w;
        }
        u64 xb[18];
#pragma unroll
        for (int j = 0; j < 18; j++) xb[j] = bcast2(x[j]);
#pragma unroll
        for (int o = 0; o < 4; o++) {
            const ulonglong2* w2 = reinterpret_cast<const ulonglong2*>(
                wp + ((size_t)o * CIN + ic) * 16);
            u64 wr[16];
#pragma unroll
            for (int q = 0; q < 8; q++) { ulonglong2 t = w2[q]; wr[2*q] = t.x; wr[2*q+1] = t.y; }
#pragma unroll
            for (int k = 0; k < 15; k++) {
                fma2(acc[o][0], wr[k], xb[k + 0]);
                fma2(acc[o][1], wr[k], xb[k + 1]);
                fma2(acc[o][2], wr[k], xb[k + 2]);
                fma2(acc[o][3], wr[k], xb[k + 3]);
            }
        }
    }

    float recf[8][4];
#pragma unroll
    for (int o = 0; o < 4; o++)
#pragma unroll
        for (int p = 0; p < 4; p++) {
            int l = l0 + p;
            float2 v = unpack2(acc[o][p]);
            if (l < L_) {
                recf[2*o    ][p] = rec[((size_t)b * C_ + 2*o    ) * L_ + l] + v.x;
                recf[2*o + 1][p] = rec[((size_t)b * C_ + 2*o + 1) * L_ + l] + v.y;
            } else {
                recf[2*o][p] = 0.0f; recf[2*o + 1][p] = 0.0f;
            }
        }

#pragma unroll
    for (int o = 0; o < 8; o++) {
        float r0 = pb[o], r1 = r0, r2 = r0, r3 = r0;
#pragma unroll
        for (int c = 0; c < 8; c++) {
            float wv = __ldg(&pw[o * C_ + c]);
            r0 += wv * recf[c][0];
            r1 += wv * recf[c][1];
            r2 += wv * recf[c][2];
            r3 += wv * recf[c][3];
        }
        size_t base = ((size_t)b * C_ + o) * L_;
        if (l0 + 0 < L_) out[base + l0 + 0] = r0;
        if (l0 + 1 < L_) out[base + l0 + 1] = r1;
        if (l0 + 2 < L_) out[base + l0 + 2] = r2;
        if (l0 + 3 < L_) out[base + l0 + 3] = r3;
    }
}

// ---------------- launcher ----------------
extern "C" void kernel_launch(void* const* d_in, const int* in_sizes, int n_in,
                              void* d_out, int out_size)
{
    const float* X   = (const float*)d_in[0];
    const float* W1  = (const float*)d_in[1];
    const float* b1  = (const float*)d_in[2];
    const float* W2  = (const float*)d_in[3];
    const float* b2  = (const float*)d_in[4];
    const float* rw1 = (const float*)d_in[5];
    const float* rb1 = (const float*)d_in[6];
    const float* rw2 = (const float*)d_in[7];
    const float* rb2 = (const float*)d_in[8];
    const float* rw3 = (const float*)d_in[9];
    const float* rb3 = (const float*)d_in[10];
    const float* pw  = (const float*)d_in[11];
    const float* pb  = (const float*)d_in[12];
    float* out = (float*)d_out;

    __nv_bfloat16 *pXh, *pXl, *pHh, *pHl, *pW1th, *pW1tl, *pW2th, *pW2tl;
    __nv_bfloat16 *pR1h, *pR1l, *pW2h, *pW2l;
    float *pPatches, *pRec, *pR2;
    u64 *pWp1, *pWp3;
    cudaGetSymbolAddress((void**)&pXh,   g_Xh);
    cudaGetSymbolAddress((void**)&pXl,   g_Xl);
    cudaGetSymbolAddress((void**)&pHh,   g_Hh);
    cudaGetSymbolAddress((void**)&pHl,   g_Hl);
    cudaGetSymbolAddress((void**)&pW1th, g_W1th);
    cudaGetSymbolAddress((void**)&pW1tl, g_W1tl);
    cudaGetSymbolAddress((void**)&pW2th, g_W2th);
    cudaGetSymbolAddress((void**)&pW2tl, g_W2tl);
    cudaGetSymbolAddress((void**)&pPatches, g_patches);
    cudaGetSymbolAddress((void**)&pRec,  g_rec);
    cudaGetSymbolAddress((void**)&pR1h,  g_r1h);
    cudaGetSymbolAddress((void**)&pR1l,  g_r1l);
    cudaGetSymbolAddress((void**)&pR2,   g_r2);
    cudaGetSymbolAddress((void**)&pWp1,  g_wp1);
    cudaGetSymbolAddress((void**)&pWp3,  g_wp3);
    cudaGetSymbolAddress((void**)&pW2h,  g_w2h);
    cudaGetSymbolAddress((void**)&pW2l,  g_w2l);

    // 0) preps
    pack_w_kernel<<<(16*8*16 + 127) / 128, 128>>>(rw1, (float2*)pWp1, 32, 8);
    pack_w_kernel<<<(4*16*16 + 127) / 128, 128>>>(rw3, (float2*)pWp3, 8, 16);
    w2_prep_kernel<<<(16*480 + 255) / 256, 256>>>(rw2, pW2h, pW2l);
    {
        int n4 = (int)((size_t)M_ * 512 / 4);
        split_f32_kernel<<<(n4 + 255) / 256, 256>>>(X, pXh, pXl, n4);
    }
    transp_split_kernel<<<(512*512 + 255) / 256, 256>>>(W1, pW1th, pW1tl, 512, 512, 512);
    transp_split_kernel<<<(256*512 + 255) / 256, 256>>>(W2, pW2th, pW2tl, 512, 200, 256);

    // 1) Hh/Hl = split(GELU(X @ W1 + b1))
    gemm_hmma<true><<<dim3(8, M_ / 128), 256>>>(
        pXh, pXl, pW1th, pW1tl, b1, 512, pHh, pHl, nullptr);

    // 2) patches = H @ W2 + b2
    gemm_hmma<false><<<dim3(4, M_ / 128), 256>>>(
        pHh, pHl, pW2th, pW2tl, b2, 200, nullptr, nullptr, pPatches);

    // 3) overlap-add -> rec
    {
        int total = B_ * C_ * L_;
        overlap_add_kernel<<<(total + 255) / 256, 256>>>(pPatches, pRec);
    }
    // 4) r1(hi/lo bf16) = split(GELU(conv1(rec)))
    {
        dim3 grid((L_ + 511) / 512, B_);
        conv1_f32x2_bf16<<<grid, 128>>>(pRec, pWp1, rb1, pR1h, pR1l);
    }
    // 5) r2 = GELU(conv2(r1))  -- implicit-GEMM HMMA
    {
        dim3 grid((L_ + 127) / 128, B_);
        conv2_hmma<<<grid, 256>>>(pR1h, pR1l, pW2h, pW2l, rb2, pR2);
    }
    // 6) out = pw @ (rec + conv3(r2)) + pb
    {
        dim3 grid((L_ + 511) / 512, B_);
        conv3_res_pw_f32x2<<<grid, 128>>>(pR2, pWp3, rb3, pRec, pw, pb, out);
    }
}

// round 7
// speedup vs baseline: 3.4537x; 1.2201x over previous
#include <cuda_runtime.h>
#include <cuda_bf16.h>
#include <math.h>
#include <stdint.h>

#define B_      1024
#define P_      11
#define C_      8
#define H_      512
#define T_      200
#define L_      2000
#define STRIDE_ 180
#define M_      (B_*P_*C_)

typedef unsigned long long u64;
typedef unsigned int u32;
typedef __nv_bfloat16 bf16;

// ---------------- scratch (device globals) ----------------
__device__ bf16 g_Xh[(size_t)M_ * 512];
__device__ bf16 g_Xl[(size_t)M_ * 512];
__device__ bf16 g_Hh[(size_t)M_ * 512];
__device__ bf16 g_Hl[(size_t)M_ * 512];
__device__ bf16 g_W1th[512 * 512];
__device__ bf16 g_W1tl[512 * 512];
__device__ bf16 g_W2th[256 * 512];
__device__ bf16 g_W2tl[256 * 512];
__device__ float g_patches[(size_t)M_ * T_];
__device__ float g_rec[(size_t)B_ * C_ * L_];
__device__ bf16 g_rech[(size_t)B_ * L_ * 8];     // rec bf16 hi [b][l][8]
__device__ bf16 g_recl[(size_t)B_ * L_ * 8];
__device__ bf16 g_r1h[(size_t)B_ * L_ * 32];     // conv1 out [b][l][32]
__device__ bf16 g_r1l[(size_t)B_ * L_ * 32];
__device__ bf16 g_r2h[(size_t)B_ * L_ * 16];     // conv2 out [b][l][16]
__device__ bf16 g_r2l[(size_t)B_ * L_ * 16];
// conv weights bf16-split
__device__ bf16 g_cw1h[32 * 128];   // [co][k16step*16 + (tap&1)*8 + ic], tap15 zero
__device__ bf16 g_cw1l[32 * 128];
__device__ bf16 g_w2h[16 * 480];    // [co][k*32+ic]
__device__ bf16 g_w2l[16 * 480];
__device__ bf16 g_cw3h[8 * 240];    // [co][k*16+ic]
__device__ bf16 g_cw3l[8 * 240];

__device__ __forceinline__ float gelu_erf(float x) {
    return 0.5f * x * (1.0f + erff(x * 0.7071067811865476f));
}

// ---------------- warp MMA primitives ----------------
__device__ __forceinline__ uint32_t smem_u32(const void* p) {
    uint32_t a;
    asm("{ .reg .u64 t; cvta.to.shared.u64 t, %1; cvt.u32.u64 %0, t; }" : "=r"(a) : "l"(p));
    return a;
}
__device__ __forceinline__ void ldsm_x4(u32& r0, u32& r1, u32& r2, u32& r3, u32 addr) {
    asm volatile("ldmatrix.sync.aligned.m8n8.x4.shared.b16 {%0,%1,%2,%3}, [%4];"
        : "=r"(r0), "=r"(r1), "=r"(r2), "=r"(r3) : "r"(addr));
}
__device__ __forceinline__ void ldsm_x2(u32& r0, u32& r1, u32 addr) {
    asm volatile("ldmatrix.sync.aligned.m8n8.x2.shared.b16 {%0,%1}, [%2];"
        : "=r"(r0), "=r"(r1) : "r"(addr));
}
__device__ __forceinline__ void mma_bf16(float* d, const u32* a, const u32* b) {
    asm volatile("mma.sync.aligned.m16n8k16.row.col.f32.bf16.bf16.f32 "
        "{%0,%1,%2,%3}, {%4,%5,%6,%7}, {%8,%9}, {%0,%1,%2,%3};"
        : "+f"(d[0]), "+f"(d[1]), "+f"(d[2]), "+f"(d[3])
        : "r"(a[0]), "r"(a[1]), "r"(a[2]), "r"(a[3]), "r"(b[0]), "r"(b[1]));
}
__device__ __forceinline__ void split_bf16(float v, bf16& h, bf16& l) {
    h = __float2bfloat16(v);
    l = __float2bfloat16(v - __bfloat162float(h));
}

// ================= prep kernels =================
__global__ void split_f32_kernel(const float* __restrict__ x,
                                 bf16* __restrict__ hh, bf16* __restrict__ hl, int n4)
{
    int i = blockIdx.x * 256 + threadIdx.x;
    if (i >= n4) return;
    float4 v = reinterpret_cast<const float4*>(x)[i];
    float f[4] = {v.x, v.y, v.z, v.w};
    bf16 h[4], l[4];
#pragma unroll
    for (int j = 0; j < 4; j++) split_bf16(f[j], h[j], l[j]);
    __nv_bfloat162* ph = reinterpret_cast<__nv_bfloat162*>(hh) + 2 * (size_t)i;
    __nv_bfloat162* pl = reinterpret_cast<__nv_bfloat162*>(hl) + 2 * (size_t)i;
    ph[0] = __halves2bfloat162(h[0], h[1]); ph[1] = __halves2bfloat162(h[2], h[3]);
    pl[0] = __halves2bfloat162(l[0], l[1]); pl[1] = __halves2bfloat162(l[2], l[3]);
}

__global__ void transp_split_kernel(const float* __restrict__ W,
                                    bf16* __restrict__ th, bf16* __restrict__ tl,
                                    int Kdim, int Nsrc, int Npad)
{
    int idx = blockIdx.x * 256 + threadIdx.x;
    if (idx >= Npad * Kdim) return;
    int n = idx / Kdim, k = idx - n * Kdim;
    float f = (n < Nsrc) ? W[(size_t)k * Nsrc + n] : 0.0f;
    split_bf16(f, th[idx], tl[idx]);
}

// rw1 (32,8,15) -> [co][128]: c = k16*16 + (tap&1)*8 + ic, tap = 2*k16 + (c>>3 & 1)
__global__ void w1c_prep_kernel(const float* __restrict__ w,
                                bf16* __restrict__ wh, bf16* __restrict__ wl)
{
    int idx = blockIdx.x * 256 + threadIdx.x;
    if (idx >= 32 * 128) return;
    int co = idx >> 7, c = idx & 127;
    int ks = c >> 4, rem = c & 15;
    int tap = 2 * ks + (rem >> 3);
    int ic = rem & 7;
    float f = (tap < 15) ? w[((size_t)co * 8 + ic) * 15 + tap] : 0.0f;
    split_bf16(f, wh[idx], wl[idx]);
}

// rw2 (16,32,15) -> [co][k*32+ic]
__global__ void w2_prep_kernel(const float* __restrict__ w,
                               bf16* __restrict__ wh, bf16* __restrict__ wl)
{
    int idx = blockIdx.x * 256 + threadIdx.x;
    if (idx >= 16 * 480) return;
    int co = idx / 480, c = idx - co * 480;
    int k = c >> 5, ic = c & 31;
    float f = w[((size_t)co * 32 + ic) * 15 + k];
    split_bf16(f, wh[idx], wl[idx]);
}

// rw3 (8,16,15) -> [co][k*16+ic]
__global__ void w3c_prep_kernel(const float* __restrict__ w,
                                bf16* __restrict__ wh, bf16* __restrict__ wl)
{
    int idx = blockIdx.x * 256 + threadIdx.x;
    if (idx >= 8 * 240) return;
    int co = idx / 240, c = idx - co * 240;
    int k = c >> 4, ic = c & 15;
    float f = w[((size_t)co * 16 + ic) * 15 + k];
    split_bf16(f, wh[idx], wl[idx]);
}

// ================= HMMA GEMM (verified core) =================
#define ASTR 40

template<bool GELU_SPLIT>
__global__ void __launch_bounds__(256, 2) gemm_hmma(
    const bf16* __restrict__ Ah, const bf16* __restrict__ Al,
    const bf16* __restrict__ Bh, const bf16* __restrict__ Bl,
    const float* __restrict__ bias, int Nvalid,
    bf16* __restrict__ outHh, bf16* __restrict__ outHl, float* __restrict__ outF)
{
    __shared__ __align__(16) bf16 sAh[128 * ASTR];
    __shared__ __align__(16) bf16 sAl[128 * ASTR];
    __shared__ __align__(16) bf16 sBh[64 * ASTR];
    __shared__ __align__(16) bf16 sBl[64 * ASTR];

    const int tid  = threadIdx.x;
    const int lane = tid & 31;
    const int wid  = tid >> 5;
    const int wm   = wid & 3;
    const int wn   = wid >> 2;
    const int bm   = blockIdx.y * 128;
    const int bn   = blockIdx.x * 64;

    float acc[2][4][4];
#pragma unroll
    for (int i = 0; i < 2; i++)
#pragma unroll
        for (int j = 0; j < 4; j++)
#pragma unroll
            for (int q = 0; q < 4; q++) acc[i][j][q] = 0.0f;

    const int ar = tid >> 2;
    const int aq = (tid & 3) * 8;
    const size_t gA0 = (size_t)(bm + ar) * 512 + aq;
    const size_t gA1 = (size_t)(bm + ar + 64) * 512 + aq;
    const size_t gB0 = (size_t)(bn + ar) * 512 + aq;

    const u32 sbAh = smem_u32(sAh), sbAl = smem_u32(sAl);
    const u32 sbBh = smem_u32(sBh), sbBl = smem_u32(sBl);

    const int lrow = lane & 15;
    const int lhalf = (lane >> 4) * 8;
    const u32 aoffA0 = ((wm * 32 +      lrow) * ASTR + lhalf) * 2;
    const u32 aoffA1 = ((wm * 32 + 16 + lrow) * ASTR + lhalf) * 2;
    const u32 aoffB0 = ((wn * 32 +      lrow) * ASTR + lhalf) * 2;
    const u32 aoffB1 = ((wn * 32 + 16 + lrow) * ASTR + lhalf) * 2;

    uint4 pah0, pah1, pal0, pal1, pbh, pbl;
    pah0 = *(const uint4*)(Ah + gA0); pah1 = *(const uint4*)(Ah + gA1);
    pal0 = *(const uint4*)(Al + gA0); pal1 = *(const uint4*)(Al + gA1);
    pbh  = *(const uint4*)(Bh + gB0); pbl  = *(const uint4*)(Bl + gB0);

    const int sA0 = ar * ASTR + aq, sA1 = (ar + 64) * ASTR + aq, sB0 = ar * ASTR + aq;

    for (int kt = 0; kt < 16; kt++) {
        *(uint4*)(sAh + sA0) = pah0; *(uint4*)(sAh + sA1) = pah1;
        *(uint4*)(sAl + sA0) = pal0; *(uint4*)(sAl + sA1) = pal1;
        *(uint4*)(sBh + sB0) = pbh;  *(uint4*)(sBl + sB0) = pbl;
        __syncthreads();

        if (kt < 15) {
            int k0 = (kt + 1) * 32;
            pah0 = *(const uint4*)(Ah + gA0 + k0); pah1 = *(const uint4*)(Ah + gA1 + k0);
            pal0 = *(const uint4*)(Al + gA0 + k0); pal1 = *(const uint4*)(Al + gA1 + k0);
            pbh  = *(const uint4*)(Bh + gB0 + k0); pbl  = *(const uint4*)(Bl + gB0 + k0);
        }

#pragma unroll
        for (int kk = 0; kk < 2; kk++) {
            const u32 kadd = kk * 32;
            u32 a_h[2][4], a_l[2][4];
            ldsm_x4(a_h[0][0], a_h[0][1], a_h[0][2], a_h[0][3], sbAh + aoffA0 + kadd);
            ldsm_x4(a_h[1][0], a_h[1][1], a_h[1][2], a_h[1][3], sbAh + aoffA1 + kadd);
            ldsm_x4(a_l[0][0], a_l[0][1], a_l[0][2], a_l[0][3], sbAl + aoffA0 + kadd);
            ldsm_x4(a_l[1][0], a_l[1][1], a_l[1][2], a_l[1][3], sbAl + aoffA1 + kadd);

            u32 t0, t1, t2, t3;
            u32 b_h[4][2], b_l[4][2];
            ldsm_x4(t0, t1, t2, t3, sbBh + aoffB0 + kadd);
            b_h[0][0] = t0; b_h[0][1] = t2; b_h[1][0] = t1; b_h[1][1] = t3;
            ldsm_x4(t0, t1, t2, t3, sbBh + aoffB1 + kadd);
            b_h[2][0] = t0; b_h[2][1] = t2; b_h[3][0] = t1; b_h[3][1] = t3;
            ldsm_x4(t0, t1, t2, t3, sbBl + aoffB0 + kadd);
            b_l[0][0] = t0; b_l[0][1] = t2; b_l[1][0] = t1; b_l[1][1] = t3;
            ldsm_x4(t0, t1, t2, t3, sbBl + aoffB1 + kadd);
            b_l[2][0] = t0; b_l[2][1] = t2; b_l[3][0] = t1; b_l[3][1] = t3;

#pragma unroll
            for (int mi = 0; mi < 2; mi++)
#pragma unroll
                for (int ni = 0; ni < 4; ni++) {
                    mma_bf16(acc[mi][ni], a_h[mi], b_h[ni]);
                    mma_bf16(acc[mi][ni], a_h[mi], b_l[ni]);
                    mma_bf16(acc[mi][ni], a_l[mi], b_h[ni]);
                }
        }
        __syncthreads();
    }

    const int grp = lane >> 2;
    const int qc  = (lane & 3) * 2;
#pragma unroll
    for (int mi = 0; mi < 2; mi++) {
        const int r0 = bm + wm * 32 + mi * 16 + grp;
        const int r1 = r0 + 8;
#pragma unroll
        for (int ni = 0; ni < 4; ni++) {
            const int col = bn + wn * 32 + ni * 8 + qc;
            float bv0 = __ldg(&bias[col]), bv1 = __ldg(&bias[col + 1]);
            float v00 = acc[mi][ni][0] + bv0, v01 = acc[mi][ni][1] + bv1;
            float v10 = acc[mi][ni][2] + bv0, v11 = acc[mi][ni][3] + bv1;
            if (GELU_SPLIT) {
                v00 = gelu_erf(v00); v01 = gelu_erf(v01);
                v10 = gelu_erf(v10); v11 = gelu_erf(v11);
                bf16 h0, h1, l0, l1;
                split_bf16(v00, h0, l0); split_bf16(v01, h1, l1);
                size_t i0 = (size_t)r0 * 256 + (col >> 1);
                reinterpret_cast<__nv_bfloat162*>(outHh)[i0] = __halves2bfloat162(h0, h1);
                reinterpret_cast<__nv_bfloat162*>(outHl)[i0] = __halves2bfloat162(l0, l1);
                split_bf16(v10, h0, l0); split_bf16(v11, h1, l1);
                size_t i1 = (size_t)r1 * 256 + (col >> 1);
                reinterpret_cast<__nv_bfloat162*>(outHh)[i1] = __halves2bfloat162(h0, h1);
                reinterpret_cast<__nv_bfloat162*>(outHl)[i1] = __halves2bfloat162(l0, l1);
            } else {
                if (col < Nvalid) {
                    *(float2*)(outF + (size_t)r0 * Nvalid + col) = make_float2(v00, v01);
                    *(float2*)(outF + (size_t)r1 * Nvalid + col) = make_float2(v10, v11);
                }
            }
        }
    }
}

// ================= overlap-add: fp32 [b][c][l] + bf16 split [b][l][8] =================
__global__ void overlap_add_v2(const float* __restrict__ patches,
                               float* __restrict__ rec,
                               bf16* __restrict__ rech, bf16* __restrict__ recl)
{
    const int b  = blockIdx.y;
    const int l  = blockIdx.x * 256 + threadIdx.x;
    if (l >= L_) return;

    int i_lo = l - (T_ - 1);
    i_lo = (i_lo > 0) ? (i_lo + STRIDE_ - 1) / STRIDE_ : 0;
    int i_hi = l / STRIDE_;
    if (i_hi > P_ - 1) i_hi = P_ - 1;

    int np = 0, pi[2], pt[2];
    float wv[2], ws = 0.0f;
    for (int i = i_lo; i <= i_hi; i++) {
        int t = l - i * STRIDE_;
        float w;
        if (t < 50)        w = (float)t * (1.0f / 49.0f);
        else if (t >= 150) w = (float)(199 - t) * (1.0f / 49.0f);
        else               w = 1.0f;
        pi[np] = i; pt[np] = t; wv[np] = w; ws += w; np++;
    }
    float ews = fmaxf(ws, 1e-8f);

    unsigned short hh[8], ll[8];
#pragma unroll
    for (int c = 0; c < 8; c++) {
        float v = 0.0f;
        for (int j = 0; j < np; j++)
            v += patches[(((size_t)b * P_ + pi[j]) * C_ + c) * T_ + pt[j]] * wv[j];
        v = v / ews;
        rec[((size_t)b * C_ + c) * L_ + l] = v;
        bf16 h, lo; split_bf16(v, h, lo);
        hh[c] = __bfloat16_as_ushort(h);
        ll[c] = __bfloat16_as_ushort(lo);
    }
    size_t o = ((size_t)b * L_ + l) * 8;
    *(uint4*)(rech + o) = *(uint4*)hh;
    *(uint4*)(recl + o) = *(uint4*)ll;
}

// ================= conv1: 8->32 k15, implicit-GEMM HMMA =================
// X rows: r <-> gp = t0+r-7; row stores x[gp][0..7] ++ x[gp+1][0..7].
// kstep k: A fragment at row p+2k covers taps 2k,2k+1.
#define C1XSTR 40
#define C1WSTR 136
__global__ void __launch_bounds__(256) conv1_hmma(
    const bf16* __restrict__ rech, const bf16* __restrict__ recl,
    const bf16* __restrict__ wh, const bf16* __restrict__ wl,
    const float* __restrict__ bias,
    bf16* __restrict__ r1h, bf16* __restrict__ r1l)
{
    __shared__ __align__(16) bf16 sXh[143 * C1XSTR];
    __shared__ __align__(16) bf16 sXl[143 * C1XSTR];
    __shared__ __align__(16) bf16 sWh[32 * C1WSTR];
    __shared__ __align__(16) bf16 sWl[32 * C1WSTR];

    const int tid  = threadIdx.x;
    const int lane = tid & 31;
    const int wm   = tid >> 5;
    const int b    = blockIdx.y;
    const int t0   = blockIdx.x * 128;

    for (int i = tid; i < 32 * 64; i += 256) {
        int r = i >> 6, q = i & 63;
        ((u32*)sWh)[r * (C1WSTR/2) + q] = ((const u32*)wh)[r * 64 + q];
        ((u32*)sWl)[r * (C1WSTR/2) + q] = ((const u32*)wl)[r * 64 + q];
    }
    for (int i = tid; i < 143 * 2; i += 256) {
        int r = i >> 1, half = i & 1;
        int gp = t0 + r - 7 + half;
        uint4 vh = make_uint4(0,0,0,0), vl = vh;
        if (gp >= 0 && gp < L_) {
            size_t o = ((size_t)b * L_ + gp) * 8;
            vh = *(const uint4*)(rech + o);
            vl = *(const uint4*)(recl + o);
        }
        *(uint4*)(sXh + r * C1XSTR + half * 8) = vh;
        *(uint4*)(sXl + r * C1XSTR + half * 8) = vl;
    }
    __syncthreads();

    const u32 sbXh = smem_u32(sXh), sbXl = smem_u32(sXl);
    const u32 sbWh = smem_u32(sWh), sbWl = smem_u32(sWl);
    const int lrow = lane & 15;
    const int lhalf = (lane >> 4) * 8;

    float acc[4][4];
#pragma unroll
    for (int ni = 0; ni < 4; ni++)
#pragma unroll
        for (int q = 0; q < 4; q++) acc[ni][q] = 0.0f;

#pragma unroll
    for (int k = 0; k < 8; k++) {
        u32 aadd = (u32)((wm * 16 + lrow + 2 * k) * C1XSTR + lhalf) * 2;
        u32 ah[4], al[4];
        ldsm_x4(ah[0], ah[1], ah[2], ah[3], sbXh + aadd);
        ldsm_x4(al[0], al[1], al[2], al[3], sbXl + aadd);

        u32 t0r, t1r, t2r, t3r;
        u32 bh[4][2], bl[4][2];
#pragma unroll
        for (int na2 = 0; na2 < 2; na2++) {
            u32 badd = (u32)((na2 * 16 + lrow) * C1WSTR + k * 16 + lhalf) * 2;
            ldsm_x4(t0r, t1r, t2r, t3r, sbWh + badd);
            bh[na2*2][0] = t0r; bh[na2*2][1] = t2r;
            bh[na2*2+1][0] = t1r; bh[na2*2+1][1] = t3r;
            ldsm_x4(t0r, t1r, t2r, t3r, sbWl + badd);
            bl[na2*2][0] = t0r; bl[na2*2][1] = t2r;
            bl[na2*2+1][0] = t1r; bl[na2*2+1][1] = t3r;
        }
#pragma unroll
        for (int ni = 0; ni < 4; ni++) {
            mma_bf16(acc[ni], ah, bh[ni]);
            mma_bf16(acc[ni], ah, bl[ni]);
            mma_bf16(acc[ni], al, bh[ni]);
        }
    }
    __syncthreads();

    // stage (aliased on X buffers): u32 bf162 pairs [128][17]
    u32* stgh = (u32*)sXh;
    u32* stgl = (u32*)sXl;
    const int grp = lane >> 2, qc = (lane & 3) * 2;
#pragma unroll
    for (int ni = 0; ni < 4; ni++) {
        int ch = ni * 8 + qc;
        float bv0 = __ldg(&bias[ch]), bv1 = __ldg(&bias[ch + 1]);
        int p0 = wm * 16 + grp, p1 = p0 + 8;
        float v00 = gelu_erf(acc[ni][0] + bv0), v01 = gelu_erf(acc[ni][1] + bv1);
        float v10 = gelu_erf(acc[ni][2] + bv0), v11 = gelu_erf(acc[ni][3] + bv1);
        bf16 h0, h1, l0, l1;
        split_bf16(v00, h0, l0); split_bf16(v01, h1, l1);
        __nv_bfloat162 th = __halves2bfloat162(h0, h1), tl = __halves2bfloat162(l0, l1);
        stgh[p0 * 17 + ni * 4 + (lane & 3)] = *(u32*)&th;
        stgl[p0 * 17 + ni * 4 + (lane & 3)] = *(u32*)&tl;
        split_bf16(v10, h0, l0); split_bf16(v11, h1, l1);
        th = __halves2bfloat162(h0, h1); tl = __halves2bfloat162(l0, l1);
        stgh[p1 * 17 + ni * 4 + (lane & 3)] = *(u32*)&th;
        stgl[p1 * 17 + ni * 4 + (lane & 3)] = *(u32*)&tl;
    }
    __syncthreads();
    for (int i = tid; i < 128 * 16; i += 256) {
        int p = i >> 4, q = i & 15;
        int l = t0 + p;
        if (l < L_) {
            size_t o = ((size_t)b * L_ + l) * 16 + q;
            ((u32*)r1h)[o] = stgh[p * 17 + q];
            ((u32*)r1l)[o] = stgl[p * 17 + q];
        }
    }
}

// ================= conv2: 32->16 k15, implicit-GEMM HMMA =================
#define X2STR 40
#define W2STR 488
__global__ void __launch_bounds__(256) conv2_hmma(
    const bf16* __restrict__ r1h, const bf16* __restrict__ r1l,
    const bf16* __restrict__ wh, const bf16* __restrict__ wl,
    const float* __restrict__ bias,
    bf16* __restrict__ r2h, bf16* __restrict__ r2l)
{
    __shared__ __align__(16) bf16 sXh[144 * X2STR];
    __shared__ __align__(16) bf16 sXl[144 * X2STR];
    __shared__ __align__(16) bf16 sWh[16 * W2STR];
    __shared__ __align__(16) bf16 sWl[16 * W2STR];

    const int tid  = threadIdx.x;
    const int lane = tid & 31;
    const int wm   = tid >> 5;
    const int b    = blockIdx.y;
    const int t0   = blockIdx.x * 128;

    for (int i = tid; i < 16 * 240; i += 256) {
        int r = i / 240, c = i - r * 240;
        ((u32*)sWh)[r * (W2STR/2) + c] = ((const u32*)wh)[r * 240 + c];
        ((u32*)sWl)[r * (W2STR/2) + c] = ((const u32*)wl)[r * 240 + c];
    }
    for (int i = tid; i < 144 * 4; i += 256) {
        int r = i >> 2, q = i & 3;
        int gp = t0 + r - 8;
        uint4 vh = make_uint4(0,0,0,0), vl = vh;
        if (gp >= 0 && gp < L_) {
            size_t o = ((size_t)b * L_ + gp) * 32 + q * 8;
            vh = *(const uint4*)(r1h + o);
            vl = *(const uint4*)(r1l + o);
        }
        *(uint4*)(sXh + r * X2STR + q * 8) = vh;
        *(uint4*)(sXl + r * X2STR + q * 8) = vl;
    }
    __syncthreads();

    const u32 sbXh = smem_u32(sXh), sbXl = smem_u32(sXl);
    const u32 sbWh = smem_u32(sWh), sbWl = smem_u32(sWl);

    float acc[2][4];
#pragma unroll
    for (int ni = 0; ni < 2; ni++)
#pragma unroll
        for (int q = 0; q < 4; q++) acc[ni][q] = 0.0f;

    const int lrow = lane & 15;
    const int lhalf = (lane >> 4) * 8;
    const u32 boff  = sbWh + ((lane & 15) * W2STR + lhalf) * 2;
    const u32 boffl = sbWl + ((lane & 15) * W2STR + lhalf) * 2;

#pragma unroll 2
    for (int ks = 0; ks < 30; ks++) {
        const int k   = ks >> 1;
        const int icb = (ks & 1) * 16;
        const u32 aadd = (u32)((wm * 16 + lrow + k + 1) * X2STR + icb + lhalf) * 2;

        u32 ah[4], al[4];
        ldsm_x4(ah[0], ah[1], ah[2], ah[3], sbXh + aadd);
        ldsm_x4(al[0], al[1], al[2], al[3], sbXl + aadd);

        u32 t0r, t1r, t2r, t3r;
        u32 bh[2][2], bl[2][2];
        ldsm_x4(t0r, t1r, t2r, t3r, boff + ks * 32);
        bh[0][0] = t0r; bh[0][1] = t2r; bh[1][0] = t1r; bh[1][1] = t3r;
        ldsm_x4(t0r, t1r, t2r, t3r, boffl + ks * 32);
        bl[0][0] = t0r; bl[0][1] = t2r; bl[1][0] = t1r; bl[1][1] = t3r;

#pragma unroll
        for (int ni = 0; ni < 2; ni++) {
            mma_bf16(acc[ni], ah, bh[ni]);
            mma_bf16(acc[ni], ah, bl[ni]);
            mma_bf16(acc[ni], al, bh[ni]);
        }
    }
    __syncthreads();

    // stage bf16-split output (aliased): u32 pairs [128][9]
    u32* stgh = (u32*)sXh;
    u32* stgl = (u32*)sXl;
    const int grp = lane >> 2, qc = (lane & 3) * 2;
#pragma unroll
    for (int ni = 0; ni < 2; ni++) {
        int ch = ni * 8 + qc;
        float bv0 = __ldg(&bias[ch]), bv1 = __ldg(&bias[ch + 1]);
        int p0 = wm * 16 + grp, p1 = p0 + 8;
        float v00 = gelu_erf(acc[ni][0] + bv0), v01 = gelu_erf(acc[ni][1] + bv1);
        float v10 = gelu_erf(acc[ni][2] + bv0), v11 = gelu_erf(acc[ni][3] + bv1);
        bf16 h0, h1, l0, l1;
        split_bf16(v00, h0, l0); split_bf16(v01, h1, l1);
        __nv_bfloat162 th = __halves2bfloat162(h0, h1), tl = __halves2bfloat162(l0, l1);
        stgh[p0 * 9 + ni * 4 + (lane & 3)] = *(u32*)&th;
        stgl[p0 * 9 + ni * 4 + (lane & 3)] = *(u32*)&tl;
        split_bf16(v10, h0, l0); split_bf16(v11, h1, l1);
        th = __halves2bfloat162(h0, h1); tl = __halves2bfloat162(l0, l1);
        stgh[p1 * 9 + ni * 4 + (lane & 3)] = *(u32*)&th;
        stgl[p1 * 9 + ni * 4 + (lane & 3)] = *(u32*)&tl;
    }
    __syncthreads();
    for (int i = tid; i < 128 * 8; i += 256) {
        int p = i >> 3, q = i & 7;
        int l = t0 + p;
        if (l < L_) {
            size_t o = ((size_t)b * L_ + l) * 8 + q;
            ((u32*)r2h)[o] = stgh[p * 9 + q];
            ((u32*)r2l)[o] = stgl[p * 9 + q];
        }
    }
}

// ================= conv3: 16->8 k15 HMMA + residual + pointwise =================
#define X3STR 40
#define W3STR 248
__global__ void __launch_bounds__(256) conv3_hmma(
    const bf16* __restrict__ r2h, const bf16* __restrict__ r2l,
    const bf16* __restrict__ wh, const bf16* __restrict__ wl,
    const float* __restrict__ bias,
    const float* __restrict__ rec,
    const float* __restrict__ pw, const float* __restrict__ pb,
    float* __restrict__ out)
{
    __shared__ __align__(16) bf16 sXh[143 * X3STR];
    __shared__ __align__(16) bf16 sXl[143 * X3STR];
    __shared__ __align__(16) bf16 sWh[8 * W3STR];
    __shared__ __align__(16) bf16 sWl[8 * W3STR];
    __shared__ float sF[128 * 9];

    const int tid  = threadIdx.x;
    const int lane = tid & 31;
    const int wm   = tid >> 5;
    const int b    = blockIdx.y;
    const int t0   = blockIdx.x * 128;

    for (int i = tid; i < 8 * 120; i += 256) {
        int r = i / 120, c = i - r * 120;
        ((u32*)sWh)[r * (W3STR/2) + c] = ((const u32*)wh)[r * 120 + c];
        ((u32*)sWl)[r * (W3STR/2) + c] = ((const u32*)wl)[r * 120 + c];
    }
    for (int i = tid; i < 143 * 2; i += 256) {
        int r = i >> 1, q = i & 1;
        int gp = t0 + r - 7;
        uint4 vh = make_uint4(0,0,0,0), vl = vh;
        if (gp >= 0 && gp < L_) {
            size_t o = ((size_t)b * L_ + gp) * 16 + q * 8;
            vh = *(const uint4*)(r2h + o);
            vl = *(const uint4*)(r2l + o);
        }
        *(uint4*)(sXh + r * X3STR + q * 8) = vh;
        *(uint4*)(sXl + r * X3STR + q * 8) = vl;
    }
    __syncthreads();

    const u32 sbXh = smem_u32(sXh), sbXl = smem_u32(sXl);
    const u32 sbWh = smem_u32(sWh), sbWl = smem_u32(sWl);
    const int lrow = lane & 15;
    const int lhalf = (lane >> 4) * 8;
    const u32 bbase = ((lane & 7) * W3STR + ((lane >> 3) & 1) * 8) * 2;

    float acc[4] = {0.f, 0.f, 0.f, 0.f};
#pragma unroll
    for (int k = 0; k < 15; k++) {
        u32 aadd = (u32)((wm * 16 + lrow + k) * X3STR + lhalf) * 2;
        u32 ah[4], al[4];
        ldsm_x4(ah[0], ah[1], ah[2], ah[3], sbXh + aadd);
        ldsm_x4(al[0], al[1], al[2], al[3], sbXl + aadd);
        u32 bh[2], bl[2];
        ldsm_x2(bh[0], bh[1], sbWh + bbase + k * 32);
        ldsm_x2(bl[0], bl[1], sbWl + bbase + k * 32);
        mma_bf16(acc, ah, bh);
        mma_bf16(acc, ah, bl);
        mma_bf16(acc, al, bh);
    }
    __syncthreads();

    const int grp = lane >> 2, qc = (lane & 3) * 2;
    {
        float bv0 = __ldg(&bias[qc]), bv1 = __ldg(&bias[qc + 1]);
        int p0 = wm * 16 + grp, p1 = p0 + 8;
        sF[p0 * 9 + qc]     = acc[0] + bv0;
        sF[p0 * 9 + qc + 1] = acc[1] + bv1;
        sF[p1 * 9 + qc]     = acc[2] + bv0;
        sF[p1 * 9 + qc + 1] = acc[3] + bv1;
    }
    __syncthreads();

    if (tid < 128) {
        int l = t0 + tid;
        if (l < L_) {
            float resid[8];
#pragma unroll
            for (int c = 0; c < 8; c++)
                resid[c] = rec[((size_t)b * C_ + c) * L_ + l] + sF[tid * 9 + c];
#pragma unroll
            for (int o = 0; o < 8; o++) {
                float v = __ldg(&pb[o]);
#pragma unroll
                for (int c = 0; c < 8; c++)
                    v += __ldg(&pw[o * C_ + c]) * resid[c];
                out[((size_t)b * C_ + o) * L_ + l] = v;
            }
        }
    }
}

// ---------------- launcher ----------------
extern "C" void kernel_launch(void* const* d_in, const int* in_sizes, int n_in,
                              void* d_out, int out_size)
{
    const float* X   = (const float*)d_in[0];
    const float* W1  = (const float*)d_in[1];
    const float* b1  = (const float*)d_in[2];
    const float* W2  = (const float*)d_in[3];
    const float* b2  = (const float*)d_in[4];
    const float* rw1 = (const float*)d_in[5];
    const float* rb1 = (const float*)d_in[6];
    const float* rw2 = (const float*)d_in[7];
    const float* rb2 = (const float*)d_in[8];
    const float* rw3 = (const float*)d_in[9];
    const float* rb3 = (const float*)d_in[10];
    const float* pw  = (const float*)d_in[11];
    const float* pb  = (const float*)d_in[12];
    float* out = (float*)d_out;

    bf16 *pXh, *pXl, *pHh, *pHl, *pW1th, *pW1tl, *pW2th, *pW2tl;
    bf16 *pRech, *pRecl, *pR1h, *pR1l, *pR2h, *pR2l;
    bf16 *pCw1h, *pCw1l, *pW2h, *pW2l, *pCw3h, *pCw3l;
    float *pPatches, *pRec;
    cudaGetSymbolAddress((void**)&pXh,   g_Xh);
    cudaGetSymbolAddress((void**)&pXl,   g_Xl);
    cudaGetSymbolAddress((void**)&pHh,   g_Hh);
    cudaGetSymbolAddress((void**)&pHl,   g_Hl);
    cudaGetSymbolAddress((void**)&pW1th, g_W1th);
    cudaGetSymbolAddress((void**)&pW1tl, g_W1tl);
    cudaGetSymbolAddress((void**)&pW2th, g_W2th);
    cudaGetSymbolAddress((void**)&pW2tl, g_W2tl);
    cudaGetSymbolAddress((void**)&pPatches, g_patches);
    cudaGetSymbolAddress((void**)&pRec,  g_rec);
    cudaGetSymbolAddress((void**)&pRech, g_rech);
    cudaGetSymbolAddress((void**)&pRecl, g_recl);
    cudaGetSymbolAddress((void**)&pR1h,  g_r1h);
    cudaGetSymbolAddress((void**)&pR1l,  g_r1l);
    cudaGetSymbolAddress((void**)&pR2h,  g_r2h);
    cudaGetSymbolAddress((void**)&pR2l,  g_r2l);
    cudaGetSymbolAddress((void**)&pCw1h, g_cw1h);
    cudaGetSymbolAddress((void**)&pCw1l, g_cw1l);
    cudaGetSymbolAddress((void**)&pW2h,  g_w2h);
    cudaGetSymbolAddress((void**)&pW2l,  g_w2l);
    cudaGetSymbolAddress((void**)&pCw3h, g_cw3h);
    cudaGetSymbolAddress((void**)&pCw3l, g_cw3l);

    // 0) preps
    w1c_prep_kernel<<<(32*128 + 255) / 256, 256>>>(rw1, pCw1h, pCw1l);
    w2_prep_kernel<<<(16*480 + 255) / 256, 256>>>(rw2, pW2h, pW2l);
    w3c_prep_kernel<<<(8*240 + 255) / 256, 256>>>(rw3, pCw3h, pCw3l);
    {
        int n4 = (int)((size_t)M_ * 512 / 4);
        split_f32_kernel<<<(n4 + 255) / 256, 256>>>(X, pXh, pXl, n4);
    }
    transp_split_kernel<<<(512*512 + 255) / 256, 256>>>(W1, pW1th, pW1tl, 512, 512, 512);
    transp_split_kernel<<<(256*512 + 255) / 256, 256>>>(W2, pW2th, pW2tl, 512, 200, 256);

    // 1) Hh/Hl = split(GELU(X @ W1 + b1))
    gemm_hmma<true><<<dim3(8, M_ / 128), 256>>>(
        pXh, pXl, pW1th, pW1tl, b1, 512, pHh, pHl, nullptr);

    // 2) patches = H @ W2 + b2
    gemm_hmma<false><<<dim3(4, M_ / 128), 256>>>(
        pHh, pHl, pW2th, pW2tl, b2, 200, nullptr, nullptr, pPatches);

    // 3) overlap-add -> rec fp32 + bf16 split
    overlap_add_v2<<<dim3((L_ + 255) / 256, B_), 256>>>(pPatches, pRec, pRech, pRecl);

    // 4) r1 = split(GELU(conv1(rec)))
    conv1_hmma<<<dim3((L_ + 127) / 128, B_), 256>>>(pRech, pRecl, pCw1h, pCw1l, rb1, pR1h, pR1l);

    // 5) r2 = split(GELU(conv2(r1)))
    conv2_hmma<<<dim3((L_ + 127) / 128, B_), 256>>>(pR1h, pR1l, pW2h, pW2l, rb2, pR2h, pR2l);

    // 6) out = pw @ (rec + conv3(r2)) + pb
    conv3_hmma<<<dim3((L_ + 127) / 128, B_), 256>>>(pR2h, pR2l, pCw3h, pCw3l, rb3, pRec, pw, pb, out);
}

// round 8
// speedup vs baseline: 3.6393x; 1.0538x over previous
#include <cuda_runtime.h>
#include <cuda_bf16.h>
#include <math.h>
#include <stdint.h>

#define B_      1024
#define P_      11
#define C_      8
#define H_      512
#define T_      200
#define L_      2000
#define STRIDE_ 180
#define M_      (B_*P_*C_)

typedef unsigned long long u64;
typedef unsigned int u32;
typedef __nv_bfloat16 bf16;

// ---------------- scratch (device globals) ----------------
__device__ bf16 g_Hh[(size_t)M_ * 512];
__device__ bf16 g_Hl[(size_t)M_ * 512];
__device__ bf16 g_W1th[512 * 512];
__device__ bf16 g_W1tl[512 * 512];
__device__ bf16 g_W2th[256 * 512];
__device__ bf16 g_W2tl[256 * 512];
__device__ float g_patches[(size_t)M_ * T_];
__device__ bf16 g_rech[(size_t)B_ * L_ * 8];     // rec bf16 hi [b][l][8]
__device__ bf16 g_recl[(size_t)B_ * L_ * 8];
__device__ bf16 g_r1h[(size_t)B_ * L_ * 32];     // conv1 out [b][l][32]
__device__ bf16 g_r1l[(size_t)B_ * L_ * 32];
__device__ bf16 g_r2h[(size_t)B_ * L_ * 16];     // conv2 out [b][l][16]
__device__ bf16 g_r2l[(size_t)B_ * L_ * 16];
__device__ bf16 g_cw1h[32 * 128];
__device__ bf16 g_cw1l[32 * 128];
__device__ bf16 g_w2h[16 * 480];
__device__ bf16 g_w2l[16 * 480];
__device__ bf16 g_cw3h[8 * 240];
__device__ bf16 g_cw3l[8 * 240];

__device__ __forceinline__ float gelu_erf(float x) {
    return 0.5f * x * (1.0f + erff(x * 0.7071067811865476f));
}

// ---------------- warp MMA primitives ----------------
__device__ __forceinline__ uint32_t smem_u32(const void* p) {
    uint32_t a;
    asm("{ .reg .u64 t; cvta.to.shared.u64 t, %1; cvt.u32.u64 %0, t; }" : "=r"(a) : "l"(p));
    return a;
}
__device__ __forceinline__ void ldsm_x4(u32& r0, u32& r1, u32& r2, u32& r3, u32 addr) {
    asm volatile("ldmatrix.sync.aligned.m8n8.x4.shared.b16 {%0,%1,%2,%3}, [%4];"
        : "=r"(r0), "=r"(r1), "=r"(r2), "=r"(r3) : "r"(addr));
}
__device__ __forceinline__ void ldsm_x2(u32& r0, u32& r1, u32 addr) {
    asm volatile("ldmatrix.sync.aligned.m8n8.x2.shared.b16 {%0,%1}, [%2];"
        : "=r"(r0), "=r"(r1) : "r"(addr));
}
__device__ __forceinline__ void mma_bf16(float* d, const u32* a, const u32* b) {
    asm volatile("mma.sync.aligned.m16n8k16.row.col.f32.bf16.bf16.f32 "
        "{%0,%1,%2,%3}, {%4,%5,%6,%7}, {%8,%9}, {%0,%1,%2,%3};"
        : "+f"(d[0]), "+f"(d[1]), "+f"(d[2]), "+f"(d[3])
        : "r"(a[0]), "r"(a[1]), "r"(a[2]), "r"(a[3]), "r"(b[0]), "r"(b[1]));
}
__device__ __forceinline__ void split_bf16(float v, bf16& h, bf16& l) {
    h = __float2bfloat16(v);
    l = __float2bfloat16(v - __bfloat162float(h));
}

// ================= prep kernels (weights only) =================
__global__ void transp_split_kernel(const float* __restrict__ W,
                                    bf16* __restrict__ th, bf16* __restrict__ tl,
                                    int Kdim, int Nsrc, int Npad)
{
    int idx = blockIdx.x * 256 + threadIdx.x;
    if (idx >= Npad * Kdim) return;
    int n = idx / Kdim, k = idx - n * Kdim;
    float f = (n < Nsrc) ? W[(size_t)k * Nsrc + n] : 0.0f;
    split_bf16(f, th[idx], tl[idx]);
}

__global__ void w1c_prep_kernel(const float* __restrict__ w,
                                bf16* __restrict__ wh, bf16* __restrict__ wl)
{
    int idx = blockIdx.x * 256 + threadIdx.x;
    if (idx >= 32 * 128) return;
    int co = idx >> 7, c = idx & 127;
    int ks = c >> 4, rem = c & 15;
    int tap = 2 * ks + (rem >> 3);
    int ic = rem & 7;
    float f = (tap < 15) ? w[((size_t)co * 8 + ic) * 15 + tap] : 0.0f;
    split_bf16(f, wh[idx], wl[idx]);
}

__global__ void w2_prep_kernel(const float* __restrict__ w,
                               bf16* __restrict__ wh, bf16* __restrict__ wl)
{
    int idx = blockIdx.x * 256 + threadIdx.x;
    if (idx >= 16 * 480) return;
    int co = idx / 480, c = idx - co * 480;
    int k = c >> 5, ic = c & 31;
    float f = w[((size_t)co * 32 + ic) * 15 + k];
    split_bf16(f, wh[idx], wl[idx]);
}

__global__ void w3c_prep_kernel(const float* __restrict__ w,
                                bf16* __restrict__ wh, bf16* __restrict__ wl)
{
    int idx = blockIdx.x * 256 + threadIdx.x;
    if (idx >= 8 * 240) return;
    int co = idx / 240, c = idx - co * 240;
    int k = c >> 4, ic = c & 15;
    float f = w[((size_t)co * 16 + ic) * 15 + k];
    split_bf16(f, wh[idx], wl[idx]);
}

// ================= HMMA GEMM =================
// A_FP32: A given as fp32 [M][512], split to bf16 hi/lo while staging smem.
#define ASTR 40

template<bool A_FP32, bool GELU_SPLIT>
__global__ void __launch_bounds__(256, 2) gemm_hmma(
    const float* __restrict__ Af,
    const bf16* __restrict__ Ah, const bf16* __restrict__ Al,
    const bf16* __restrict__ Bh, const bf16* __restrict__ Bl,
    const float* __restrict__ bias, int Nvalid,
    bf16* __restrict__ outHh, bf16* __restrict__ outHl, float* __restrict__ outF)
{
    __shared__ __align__(16) bf16 sAh[128 * ASTR];
    __shared__ __align__(16) bf16 sAl[128 * ASTR];
    __shared__ __align__(16) bf16 sBh[64 * ASTR];
    __shared__ __align__(16) bf16 sBl[64 * ASTR];

    const int tid  = threadIdx.x;
    const int lane = tid & 31;
    const int wid  = tid >> 5;
    const int wm   = wid & 3;
    const int wn   = wid >> 2;
    const int bm   = blockIdx.y * 128;
    const int bn   = blockIdx.x * 64;

    float acc[2][4][4];
#pragma unroll
    for (int i = 0; i < 2; i++)
#pragma unroll
        for (int j = 0; j < 4; j++)
#pragma unroll
            for (int q = 0; q < 4; q++) acc[i][j][q] = 0.0f;

    const int ar = tid >> 2;
    const int aq = (tid & 3) * 8;
    const size_t gA0 = (size_t)(bm + ar) * 512 + aq;
    const size_t gA1 = (size_t)(bm + ar + 64) * 512 + aq;
    const size_t gB0 = (size_t)(bn + ar) * 512 + aq;

    const u32 sbAh = smem_u32(sAh), sbAl = smem_u32(sAl);
    const u32 sbBh = smem_u32(sBh), sbBl = smem_u32(sBl);

    const int lrow = lane & 15;
    const int lhalf = (lane >> 4) * 8;
    const u32 aoffA0 = ((wm * 32 +      lrow) * ASTR + lhalf) * 2;
    const u32 aoffA1 = ((wm * 32 + 16 + lrow) * ASTR + lhalf) * 2;
    const u32 aoffB0 = ((wn * 32 +      lrow) * ASTR + lhalf) * 2;
    const u32 aoffB1 = ((wn * 32 + 16 + lrow) * ASTR + lhalf) * 2;

    // prefetch registers
    uint4 pah0, pah1, pal0, pal1;
    float4 fa0, fa1, fb0, fb1;
    uint4 pbh, pbl;

    if (A_FP32) {
        fa0 = *(const float4*)(Af + gA0); fa1 = *(const float4*)(Af + gA0 + 4);
        fb0 = *(const float4*)(Af + gA1); fb1 = *(const float4*)(Af + gA1 + 4);
    } else {
        pah0 = *(const uint4*)(Ah + gA0); pah1 = *(const uint4*)(Ah + gA1);
        pal0 = *(const uint4*)(Al + gA0); pal1 = *(const uint4*)(Al + gA1);
    }
    pbh = *(const uint4*)(Bh + gB0); pbl = *(const uint4*)(Bl + gB0);

    const int sA0 = ar * ASTR + aq, sA1 = (ar + 64) * ASTR + aq, sB0 = ar * ASTR + aq;

    for (int kt = 0; kt < 16; kt++) {
        if (A_FP32) {
            float f0[8] = {fa0.x, fa0.y, fa0.z, fa0.w, fa1.x, fa1.y, fa1.z, fa1.w};
            float f1[8] = {fb0.x, fb0.y, fb0.z, fb0.w, fb1.x, fb1.y, fb1.z, fb1.w};
            unsigned short h0[8], l0[8], h1[8], l1[8];
#pragma unroll
            for (int j = 0; j < 8; j++) {
                bf16 h, l;
                split_bf16(f0[j], h, l);
                h0[j] = __bfloat16_as_ushort(h); l0[j] = __bfloat16_as_ushort(l);
                split_bf16(f1[j], h, l);
                h1[j] = __bfloat16_as_ushort(h); l1[j] = __bfloat16_as_ushort(l);
            }
            *(uint4*)(sAh + sA0) = *(uint4*)h0; *(uint4*)(sAl + sA0) = *(uint4*)l0;
            *(uint4*)(sAh + sA1) = *(uint4*)h1; *(uint4*)(sAl + sA1) = *(uint4*)l1;
        } else {
            *(uint4*)(sAh + sA0) = pah0; *(uint4*)(sAh + sA1) = pah1;
            *(uint4*)(sAl + sA0) = pal0; *(uint4*)(sAl + sA1) = pal1;
        }
        *(uint4*)(sBh + sB0) = pbh; *(uint4*)(sBl + sB0) = pbl;
        __syncthreads();

        if (kt < 15) {
            int k0 = (kt + 1) * 32;
            if (A_FP32) {
                fa0 = *(const float4*)(Af + gA0 + k0); fa1 = *(const float4*)(Af + gA0 + k0 + 4);
                fb0 = *(const float4*)(Af + gA1 + k0); fb1 = *(const float4*)(Af + gA1 + k0 + 4);
            } else {
                pah0 = *(const uint4*)(Ah + gA0 + k0); pah1 = *(const uint4*)(Ah + gA1 + k0);
                pal0 = *(const uint4*)(Al + gA0 + k0); pal1 = *(const uint4*)(Al + gA1 + k0);
            }
            pbh = *(const uint4*)(Bh + gB0 + k0); pbl = *(const uint4*)(Bl + gB0 + k0);
        }

#pragma unroll
        for (int kk = 0; kk < 2; kk++) {
            const u32 kadd = kk * 32;
            u32 a_h[2][4], a_l[2][4];
            ldsm_x4(a_h[0][0], a_h[0][1], a_h[0][2], a_h[0][3], sbAh + aoffA0 + kadd);
            ldsm_x4(a_h[1][0], a_h[1][1], a_h[1][2], a_h[1][3], sbAh + aoffA1 + kadd);
            ldsm_x4(a_l[0][0], a_l[0][1], a_l[0][2], a_l[0][3], sbAl + aoffA0 + kadd);
            ldsm_x4(a_l[1][0], a_l[1][1], a_l[1][2], a_l[1][3], sbAl + aoffA1 + kadd);

            u32 t0, t1, t2, t3;
            u32 b_h[4][2], b_l[4][2];
            ldsm_x4(t0, t1, t2, t3, sbBh + aoffB0 + kadd);
            b_h[0][0] = t0; b_h[0][1] = t2; b_h[1][0] = t1; b_h[1][1] = t3;
            ldsm_x4(t0, t1, t2, t3, sbBh + aoffB1 + kadd);
            b_h[2][0] = t0; b_h[2][1] = t2; b_h[3][0] = t1; b_h[3][1] = t3;
            ldsm_x4(t0, t1, t2, t3, sbBl + aoffB0 + kadd);
            b_l[0][0] = t0; b_l[0][1] = t2; b_l[1][0] = t1; b_l[1][1] = t3;
            ldsm_x4(t0, t1, t2, t3, sbBl + aoffB1 + kadd);
            b_l[2][0] = t0; b_l[2][1] = t2; b_l[3][0] = t1; b_l[3][1] = t3;

#pragma unroll
            for (int mi = 0; mi < 2; mi++)
#pragma unroll
                for (int ni = 0; ni < 4; ni++) {
                    mma_bf16(acc[mi][ni], a_h[mi], b_h[ni]);
                    mma_bf16(acc[mi][ni], a_h[mi], b_l[ni]);
                    mma_bf16(acc[mi][ni], a_l[mi], b_h[ni]);
                }
        }
        __syncthreads();
    }

    const int grp = lane >> 2;
    const int qc  = (lane & 3) * 2;
#pragma unroll
    for (int mi = 0; mi < 2; mi++) {
        const int r0 = bm + wm * 32 + mi * 16 + grp;
        const int r1 = r0 + 8;
#pragma unroll
        for (int ni = 0; ni < 4; ni++) {
            const int col = bn + wn * 32 + ni * 8 + qc;
            float bv0 = __ldg(&bias[col]), bv1 = __ldg(&bias[col + 1]);
            float v00 = acc[mi][ni][0] + bv0, v01 = acc[mi][ni][1] + bv1;
            float v10 = acc[mi][ni][2] + bv0, v11 = acc[mi][ni][3] + bv1;
            if (GELU_SPLIT) {
                v00 = gelu_erf(v00); v01 = gelu_erf(v01);
                v10 = gelu_erf(v10); v11 = gelu_erf(v11);
                bf16 h0, h1, l0, l1;
                split_bf16(v00, h0, l0); split_bf16(v01, h1, l1);
                size_t i0 = (size_t)r0 * 256 + (col >> 1);
                reinterpret_cast<__nv_bfloat162*>(outHh)[i0] = __halves2bfloat162(h0, h1);
                reinterpret_cast<__nv_bfloat162*>(outHl)[i0] = __halves2bfloat162(l0, l1);
                split_bf16(v10, h0, l0); split_bf16(v11, h1, l1);
                size_t i1 = (size_t)r1 * 256 + (col >> 1);
                reinterpret_cast<__nv_bfloat162*>(outHh)[i1] = __halves2bfloat162(h0, h1);
                reinterpret_cast<__nv_bfloat162*>(outHl)[i1] = __halves2bfloat162(l0, l1);
            } else {
                if (col < Nvalid) {
                    *(float2*)(outF + (size_t)r0 * Nvalid + col) = make_float2(v00, v01);
                    *(float2*)(outF + (size_t)r1 * Nvalid + col) = make_float2(v10, v11);
                }
            }
        }
    }
}

// ================= overlap-add -> rec bf16 split [b][l][8] only =================
__global__ void overlap_add_v3(const float* __restrict__ patches,
                               bf16* __restrict__ rech, bf16* __restrict__ recl)
{
    const int b  = blockIdx.y;
    const int l  = blockIdx.x * 256 + threadIdx.x;
    if (l >= L_) return;

    int i_lo = l - (T_ - 1);
    i_lo = (i_lo > 0) ? (i_lo + STRIDE_ - 1) / STRIDE_ : 0;
    int i_hi = l / STRIDE_;
    if (i_hi > P_ - 1) i_hi = P_ - 1;

    int np = 0, pi[2], pt[2];
    float wv[2], ws = 0.0f;
    for (int i = i_lo; i <= i_hi; i++) {
        int t = l - i * STRIDE_;
        float w;
        if (t < 50)        w = (float)t * (1.0f / 49.0f);
        else if (t >= 150) w = (float)(199 - t) * (1.0f / 49.0f);
        else               w = 1.0f;
        pi[np] = i; pt[np] = t; wv[np] = w; ws += w; np++;
    }
    float ews = fmaxf(ws, 1e-8f);

    unsigned short hh[8], ll[8];
#pragma unroll
    for (int c = 0; c < 8; c++) {
        float v = 0.0f;
        for (int j = 0; j < np; j++)
            v += patches[(((size_t)b * P_ + pi[j]) * C_ + c) * T_ + pt[j]] * wv[j];
        v = v / ews;
        bf16 h, lo; split_bf16(v, h, lo);
        hh[c] = __bfloat16_as_ushort(h);
        ll[c] = __bfloat16_as_ushort(lo);
    }
    size_t o = ((size_t)b * L_ + l) * 8;
    *(uint4*)(rech + o) = *(uint4*)hh;
    *(uint4*)(recl + o) = *(uint4*)ll;
}

// ================= conv1: 8->32 k15, implicit-GEMM HMMA, 2 tiles/CTA =================
#define C1XSTR 40
#define C1WSTR 136
__global__ void __launch_bounds__(256) conv1_hmma(
    const bf16* __restrict__ rech, const bf16* __restrict__ recl,
    const bf16* __restrict__ wh, const bf16* __restrict__ wl,
    const float* __restrict__ bias,
    bf16* __restrict__ r1h, bf16* __restrict__ r1l)
{
    __shared__ __align__(16) bf16 sXh[143 * C1XSTR];
    __shared__ __align__(16) bf16 sXl[143 * C1XSTR];
    __shared__ __align__(16) bf16 sWh[32 * C1WSTR];
    __shared__ __align__(16) bf16 sWl[32 * C1WSTR];

    const int tid  = threadIdx.x;
    const int lane = tid & 31;
    const int wm   = tid >> 5;
    const int b    = blockIdx.y;

    for (int i = tid; i < 32 * 64; i += 256) {
        int r = i >> 6, q = i & 63;
        ((u32*)sWh)[r * (C1WSTR/2) + q] = ((const u32*)wh)[r * 64 + q];
        ((u32*)sWl)[r * (C1WSTR/2) + q] = ((const u32*)wl)[r * 64 + q];
    }

    const u32 sbXh = smem_u32(sXh), sbXl = smem_u32(sXl);
    const u32 sbWh = smem_u32(sWh), sbWl = smem_u32(sWl);
    const int lrow = lane & 15;
    const int lhalf = (lane >> 4) * 8;
    const int grp = lane >> 2, qc = (lane & 3) * 2;

    for (int tile = 0; tile < 2; tile++) {
        const int t0 = blockIdx.x * 256 + tile * 128;
        __syncthreads();       // prior epilogue-staging reads/stores complete
        for (int i = tid; i < 143 * 2; i += 256) {
            int r = i >> 1, half = i & 1;
            int gp = t0 + r - 7 + half;
            uint4 vh = make_uint4(0,0,0,0), vl = vh;
            if (gp >= 0 && gp < L_) {
                size_t o = ((size_t)b * L_ + gp) * 8;
                vh = *(const uint4*)(rech + o);
                vl = *(const uint4*)(recl + o);
            }
            *(uint4*)(sXh + r * C1XSTR + half * 8) = vh;
            *(uint4*)(sXl + r * C1XSTR + half * 8) = vl;
        }
        __syncthreads();

        float acc[4][4];
#pragma unroll
        for (int ni = 0; ni < 4; ni++)
#pragma unroll
            for (int q = 0; q < 4; q++) acc[ni][q] = 0.0f;

#pragma unroll
        for (int k = 0; k < 8; k++) {
            u32 aadd = (u32)((wm * 16 + lrow + 2 * k) * C1XSTR + lhalf) * 2;
            u32 ah[4], al[4];
            ldsm_x4(ah[0], ah[1], ah[2], ah[3], sbXh + aadd);
            ldsm_x4(al[0], al[1], al[2], al[3], sbXl + aadd);

            u32 t0r, t1r, t2r, t3r;
            u32 bh[4][2], bl[4][2];
#pragma unroll
            for (int na2 = 0; na2 < 2; na2++) {
                u32 badd = (u32)((na2 * 16 + lrow) * C1WSTR + k * 16 + lhalf) * 2;
                ldsm_x4(t0r, t1r, t2r, t3r, sbWh + badd);
                bh[na2*2][0] = t0r; bh[na2*2][1] = t2r;
                bh[na2*2+1][0] = t1r; bh[na2*2+1][1] = t3r;
                ldsm_x4(t0r, t1r, t2r, t3r, sbWl + badd);
                bl[na2*2][0] = t0r; bl[na2*2][1] = t2r;
                bl[na2*2+1][0] = t1r; bl[na2*2+1][1] = t3r;
            }
#pragma unroll
            for (int ni = 0; ni < 4; ni++) {
                mma_bf16(acc[ni], ah, bh[ni]);
                mma_bf16(acc[ni], ah, bl[ni]);
                mma_bf16(acc[ni], al, bh[ni]);
            }
        }
        __syncthreads();

        u32* stgh = (u32*)sXh;
        u32* stgl = (u32*)sXl;
#pragma unroll
        for (int ni = 0; ni < 4; ni++) {
            int ch = ni * 8 + qc;
            float bv0 = __ldg(&bias[ch]), bv1 = __ldg(&bias[ch + 1]);
            int p0 = wm * 16 + grp, p1 = p0 + 8;
            float v00 = gelu_erf(acc[ni][0] + bv0), v01 = gelu_erf(acc[ni][1] + bv1);
            float v10 = gelu_erf(acc[ni][2] + bv0), v11 = gelu_erf(acc[ni][3] + bv1);
            bf16 h0, h1, l0, l1;
            split_bf16(v00, h0, l0); split_bf16(v01, h1, l1);
            __nv_bfloat162 th = __halves2bfloat162(h0, h1), tl = __halves2bfloat162(l0, l1);
            stgh[p0 * 17 + ni * 4 + (lane & 3)] = *(u32*)&th;
            stgl[p0 * 17 + ni * 4 + (lane & 3)] = *(u32*)&tl;
            split_bf16(v10, h0, l0); split_bf16(v11, h1, l1);
            th = __halves2bfloat162(h0, h1); tl = __halves2bfloat162(l0, l1);
            stgh[p1 * 17 + ni * 4 + (lane & 3)] = *(u32*)&th;
            stgl[p1 * 17 + ni * 4 + (lane & 3)] = *(u32*)&tl;
        }
        __syncthreads();
        for (int i = tid; i < 128 * 16; i += 256) {
            int p = i >> 4, q = i & 15;
            int l = t0 + p;
            if (l < L_) {
                size_t o = ((size_t)b * L_ + l) * 16 + q;
                ((u32*)r1h)[o] = stgh[p * 17 + q];
                ((u32*)r1l)[o] = stgl[p * 17 + q];
            }
        }
    }
}

// ================= conv2: 32->16 k15, implicit-GEMM HMMA, 2 tiles/CTA =================
#define X2STR 40
#define W2STR 488
__global__ void __launch_bounds__(256) conv2_hmma(
    const bf16* __restrict__ r1h, const bf16* __restrict__ r1l,
    const bf16* __restrict__ wh, const bf16* __restrict__ wl,
    const float* __restrict__ bias,
    bf16* __restrict__ r2h, bf16* __restrict__ r2l)
{
    __shared__ __align__(16) bf16 sXh[144 * X2STR];
    __shared__ __align__(16) bf16 sXl[144 * X2STR];
    __shared__ __align__(16) bf16 sWh[16 * W2STR];
    __shared__ __align__(16) bf16 sWl[16 * W2STR];

    const int tid  = threadIdx.x;
    const int lane = tid & 31;
    const int wm   = tid >> 5;
    const int b    = blockIdx.y;

    for (int i = tid; i < 16 * 240; i += 256) {
        int r = i / 240, c = i - r * 240;
        ((u32*)sWh)[r * (W2STR/2) + c] = ((const u32*)wh)[r * 240 + c];
        ((u32*)sWl)[r * (W2STR/2) + c] = ((const u32*)wl)[r * 240 + c];
    }

    const u32 sbXh = smem_u32(sXh), sbXl = smem_u32(sXl);
    const u32 sbWh = smem_u32(sWh), sbWl = smem_u32(sWl);
    const int lrow = lane & 15;
    const int lhalf = (lane >> 4) * 8;
    const u32 boff  = sbWh + ((lane & 15) * W2STR + lhalf) * 2;
    const u32 boffl = sbWl + ((lane & 15) * W2STR + lhalf) * 2;
    const int grp = lane >> 2, qc = (lane & 3) * 2;

    for (int tile = 0; tile < 2; tile++) {
        const int t0 = blockIdx.x * 256 + tile * 128;
        __syncthreads();
        for (int i = tid; i < 144 * 4; i += 256) {
            int r = i >> 2, q = i & 3;
            int gp = t0 + r - 8;
            uint4 vh = make_uint4(0,0,0,0), vl = vh;
            if (gp >= 0 && gp < L_) {
                size_t o = ((size_t)b * L_ + gp) * 32 + q * 8;
                vh = *(const uint4*)(r1h + o);
                vl = *(const uint4*)(r1l + o);
            }
            *(uint4*)(sXh + r * X2STR + q * 8) = vh;
            *(uint4*)(sXl + r * X2STR + q * 8) = vl;
        }
        __syncthreads();

        float acc[2][4];
#pragma unroll
        for (int ni = 0; ni < 2; ni++)
#pragma unroll
            for (int q = 0; q < 4; q++) acc[ni][q] = 0.0f;

#pragma unroll 2
        for (int ks = 0; ks < 30; ks++) {
            const int k   = ks >> 1;
            const int icb = (ks & 1) * 16;
            const u32 aadd = (u32)((wm * 16 + lrow + k + 1) * X2STR + icb + lhalf) * 2;

            u32 ah[4], al[4];
            ldsm_x4(ah[0], ah[1], ah[2], ah[3], sbXh + aadd);
            ldsm_x4(al[0], al[1], al[2], al[3], sbXl + aadd);

            u32 t0r, t1r, t2r, t3r;
            u32 bh[2][2], bl[2][2];
            ldsm_x4(t0r, t1r, t2r, t3r, boff + ks * 32);
            bh[0][0] = t0r; bh[0][1] = t2r; bh[1][0] = t1r; bh[1][1] = t3r;
            ldsm_x4(t0r, t1r, t2r, t3r, boffl + ks * 32);
            bl[0][0] = t0r; bl[0][1] = t2r; bl[1][0] = t1r; bl[1][1] = t3r;

#pragma unroll
            for (int ni = 0; ni < 2; ni++) {
                mma_bf16(acc[ni], ah, bh[ni]);
                mma_bf16(acc[ni], ah, bl[ni]);
                mma_bf16(acc[ni], al, bh[ni]);
            }
        }
        __syncthreads();

        u32* stgh = (u32*)sXh;
        u32* stgl = (u32*)sXl;
#pragma unroll
        for (int ni = 0; ni < 2; ni++) {
            int ch = ni * 8 + qc;
            float bv0 = __ldg(&bias[ch]), bv1 = __ldg(&bias[ch + 1]);
            int p0 = wm * 16 + grp, p1 = p0 + 8;
            float v00 = gelu_erf(acc[ni][0] + bv0), v01 = gelu_erf(acc[ni][1] + bv1);
            float v10 = gelu_erf(acc[ni][2] + bv0), v11 = gelu_erf(acc[ni][3] + bv1);
            bf16 h0, h1, l0, l1;
            split_bf16(v00, h0, l0); split_bf16(v01, h1, l1);
            __nv_bfloat162 th = __halves2bfloat162(h0, h1), tl = __halves2bfloat162(l0, l1);
            stgh[p0 * 9 + ni * 4 + (lane & 3)] = *(u32*)&th;
            stgl[p0 * 9 + ni * 4 + (lane & 3)] = *(u32*)&tl;
            split_bf16(v10, h0, l0); split_bf16(v11, h1, l1);
            th = __halves2bfloat162(h0, h1); tl = __halves2bfloat162(l0, l1);
            stgh[p1 * 9 + ni * 4 + (lane & 3)] = *(u32*)&th;
            stgl[p1 * 9 + ni * 4 + (lane & 3)] = *(u32*)&tl;
        }
        __syncthreads();
        for (int i = tid; i < 128 * 8; i += 256) {
            int p = i >> 3, q = i & 7;
            int l = t0 + p;
            if (l < L_) {
                size_t o = ((size_t)b * L_ + l) * 8 + q;
                ((u32*)r2h)[o] = stgh[p * 9 + q];
                ((u32*)r2l)[o] = stgl[p * 9 + q];
            }
        }
    }
}

// ================= conv3: 16->8 k15 HMMA + residual + pointwise, 2 tiles/CTA =================
#define X3STR 40
#define W3STR 248
__global__ void __launch_bounds__(256) conv3_hmma(
    const bf16* __restrict__ r2h, const bf16* __restrict__ r2l,
    const bf16* __restrict__ wh, const bf16* __restrict__ wl,
    const float* __restrict__ bias,
    const bf16* __restrict__ rech, const bf16* __restrict__ recl,
    const float* __restrict__ pw, const float* __restrict__ pb,
    float* __restrict__ out)
{
    __shared__ __align__(16) bf16 sXh[143 * X3STR];
    __shared__ __align__(16) bf16 sXl[143 * X3STR];
    __shared__ __align__(16) bf16 sWh[8 * W3STR];
    __shared__ __align__(16) bf16 sWl[8 * W3STR];
    __shared__ float sF[128 * 9];

    const int tid  = threadIdx.x;
    const int lane = tid & 31;
    const int wm   = tid >> 5;
    const int b    = blockIdx.y;

    for (int i = tid; i < 8 * 120; i += 256) {
        int r = i / 120, c = i - r * 120;
        ((u32*)sWh)[r * (W3STR/2) + c] = ((const u32*)wh)[r * 120 + c];
        ((u32*)sWl)[r * (W3STR/2) + c] = ((const u32*)wl)[r * 120 + c];
    }

    const u32 sbXh = smem_u32(sXh), sbXl = smem_u32(sXl);
    const u32 sbWh = smem_u32(sWh), sbWl = smem_u32(sWl);
    const int lrow = lane & 15;
    const int lhalf = (lane >> 4) * 8;
    const u32 bbase = ((lane & 7) * W3STR + ((lane >> 3) & 1) * 8) * 2;
    const int grp = lane >> 2, qc = (lane & 3) * 2;

    for (int tile = 0; tile < 2; tile++) {
        const int t0 = blockIdx.x * 256 + tile * 128;
        __syncthreads();
        for (int i = tid; i < 143 * 2; i += 256) {
            int r = i >> 1, q = i & 1;
            int gp = t0 + r - 7;
            uint4 vh = make_uint4(0,0,0,0), vl = vh;
            if (gp >= 0 && gp < L_) {
                size_t o = ((size_t)b * L_ + gp) * 16 + q * 8;
                vh = *(const uint4*)(r2h + o);
                vl = *(const uint4*)(r2l + o);
            }
            *(uint4*)(sXh + r * X3STR + q * 8) = vh;
            *(uint4*)(sXl + r * X3STR + q * 8) = vl;
        }
        __syncthreads();

        float acc[4] = {0.f, 0.f, 0.f, 0.f};
#pragma unroll
        for (int k = 0; k < 15; k++) {
            u32 aadd = (u32)((wm * 16 + lrow + k) * X3STR + lhalf) * 2;
            u32 ah[4], al[4];
            ldsm_x4(ah[0], ah[1], ah[2], ah[3], sbXh + aadd);
            ldsm_x4(al[0], al[1], al[2], al[3], sbXl + aadd);
            u32 bh[2], bl[2];
            ldsm_x2(bh[0], bh[1], sbWh + bbase + k * 32);
            ldsm_x2(bl[0], bl[1], sbWl + bbase + k * 32);
            mma_bf16(acc, ah, bh);
            mma_bf16(acc, ah, bl);
            mma_bf16(acc, al, bh);
        }
        __syncthreads();

        {
            float bv0 = __ldg(&bias[qc]), bv1 = __ldg(&bias[qc + 1]);
            int p0 = wm * 16 + grp, p1 = p0 + 8;
            sF[p0 * 9 + qc]     = acc[0] + bv0;
            sF[p0 * 9 + qc + 1] = acc[1] + bv1;
            sF[p1 * 9 + qc]     = acc[2] + bv0;
            sF[p1 * 9 + qc + 1] = acc[3] + bv1;
        }
        __syncthreads();

        if (tid < 128) {
            int l = t0 + tid;
            if (l < L_) {
                size_t ro = ((size_t)b * L_ + l) * 8;
                uint4 vh = *(const uint4*)(rech + ro);
                uint4 vl = *(const uint4*)(recl + ro);
                const unsigned short* hs = (const unsigned short*)&vh;
                const unsigned short* ls = (const unsigned short*)&vl;
                float resid[8];
#pragma unroll
                for (int c = 0; c < 8; c++) {
                    float rv = __bfloat162float(__ushort_as_bfloat16(hs[c]))
                             + __bfloat162float(__ushort_as_bfloat16(ls[c]));
                    resid[c] = rv + sF[tid * 9 + c];
                }
#pragma unroll
                for (int o = 0; o < 8; o++) {
                    float v = __ldg(&pb[o]);
#pragma unroll
                    for (int c = 0; c < 8; c++)
                        v += __ldg(&pw[o * C_ + c]) * resid[c];
                    out[((size_t)b * C_ + o) * L_ + l] = v;
                }
            }
        }
    }
}

// ---------------- launcher ----------------
extern "C" void kernel_launch(void* const* d_in, const int* in_sizes, int n_in,
                              void* d_out, int out_size)
{
    const float* X   = (const float*)d_in[0];
    const float* W1  = (const float*)d_in[1];
    const float* b1  = (const float*)d_in[2];
    const float* W2  = (const float*)d_in[3];
    const float* b2  = (const float*)d_in[4];
    const float* rw1 = (const float*)d_in[5];
    const float* rb1 = (const float*)d_in[6];
    const float* rw2 = (const float*)d_in[7];
    const float* rb2 = (const float*)d_in[8];
    const float* rw3 = (const float*)d_in[9];
    const float* rb3 = (const float*)d_in[10];
    const float* pw  = (const float*)d_in[11];
    const float* pb  = (const float*)d_in[12];
    float* out = (float*)d_out;

    bf16 *pHh, *pHl, *pW1th, *pW1tl, *pW2th, *pW2tl;
    bf16 *pRech, *pRecl, *pR1h, *pR1l, *pR2h, *pR2l;
    bf16 *pCw1h, *pCw1l, *pW2h, *pW2l, *pCw3h, *pCw3l;
    float *pPatches;
    cudaGetSymbolAddress((void**)&pHh,   g_Hh);
    cudaGetSymbolAddress((void**)&pHl,   g_Hl);
    cudaGetSymbolAddress((void**)&pW1th, g_W1th);
    cudaGetSymbolAddress((void**)&pW1tl, g_W1tl);
    cudaGetSymbolAddress((void**)&pW2th, g_W2th);
    cudaGetSymbolAddress((void**)&pW2tl, g_W2tl);
    cudaGetSymbolAddress((void**)&pPatches, g_patches);
    cudaGetSymbolAddress((void**)&pRech, g_rech);
    cudaGetSymbolAddress((void**)&pRecl, g_recl);
    cudaGetSymbolAddress((void**)&pR1h,  g_r1h);
    cudaGetSymbolAddress((void**)&pR1l,  g_r1l);
    cudaGetSymbolAddress((void**)&pR2h,  g_r2h);
    cudaGetSymbolAddress((void**)&pR2l,  g_r2l);
    cudaGetSymbolAddress((void**)&pCw1h, g_cw1h);
    cudaGetSymbolAddress((void**)&pCw1l, g_cw1l);
    cudaGetSymbolAddress((void**)&pW2h,  g_w2h);
    cudaGetSymbolAddress((void**)&pW2l,  g_w2l);
    cudaGetSymbolAddress((void**)&pCw3h, g_cw3h);
    cudaGetSymbolAddress((void**)&pCw3l, g_cw3l);

    // 0) weight preps
    w1c_prep_kernel<<<(32*128 + 255) / 256, 256>>>(rw1, pCw1h, pCw1l);
    w2_prep_kernel<<<(16*480 + 255) / 256, 256>>>(rw2, pW2h, pW2l);
    w3c_prep_kernel<<<(8*240 + 255) / 256, 256>>>(rw3, pCw3h, pCw3l);
    transp_split_kernel<<<(512*512 + 255) / 256, 256>>>(W1, pW1th, pW1tl, 512, 512, 512);
    transp_split_kernel<<<(256*512 + 255) / 256, 256>>>(W2, pW2th, pW2tl, 512, 200, 256);

    // 1) Hh/Hl = split(GELU(X @ W1 + b1))  -- X fp32 split fused in loader
    gemm_hmma<true, true><<<dim3(8, M_ / 128), 256>>>(
        X, nullptr, nullptr, pW1th, pW1tl, b1, 512, pHh, pHl, nullptr);

    // 2) patches = H @ W2 + b2
    gemm_hmma<false, false><<<dim3(4, M_ / 128), 256>>>(
        nullptr, pHh, pHl, pW2th, pW2tl, b2, 200, nullptr, nullptr, pPatches);

    // 3) overlap-add -> rec bf16 split
    overlap_add_v3<<<dim3((L_ + 255) / 256, B_), 256>>>(pPatches, pRech, pRecl);

    // 4) r1 = split(GELU(conv1(rec)))
    conv1_hmma<<<dim3((L_ + 255) / 256, B_), 256>>>(pRech, pRecl, pCw1h, pCw1l, rb1, pR1h, pR1l);

    // 5) r2 = split(GELU(conv2(r1)))
    conv2_hmma<<<dim3((L_ + 255) / 256, B_), 256>>>(pR1h, pR1l, pW2h, pW2l, rb2, pR2h, pR2l);

    // 6) out = pw @ (rec + conv3(r2)) + pb
    conv3_hmma<<<dim3((L_ + 255) / 256, B_), 256>>>(pR2h, pR2l, pCw3h, pCw3l, rb3,
                                                    pRech, pRecl, pw, pb, out);
}